// round 9
// baseline (speedup 1.0000x reference)
#include <cuda_runtime.h>
#include <cuda_fp16.h>
#include <cstdint>

// ---------------------------------------------------------------------------
// Problem constants
// ---------------------------------------------------------------------------
#define NB     4
#define S_LEN  8192
#define E_DIM  1024
#define M_TOT  (NB * S_LEN)   // 32768

// ---------------------------------------------------------------------------
// GEMM tiling: block 128x256, warp tile 64x64, BK=128 halves, 2-stage pipeline
// ---------------------------------------------------------------------------
#define BM 128
#define BN 256
#define BKH 128                    // K per stage in halves (256 B rows)
#define LDH 136                    // padded smem row stride (halves): bank 4r%32
#define A_H (BM * LDH)             // 17408 halves
#define B_H (BN * LDH)             // 34816 halves
#define STG_H (A_H + B_H)          // 52224 halves / stage
#define NSTAGE 2
#define SMEM_BYTES (NSTAGE * STG_H * 2)   // 208896 B
#define NSTG (E_DIM / BKH)         // 8 k-stages

// ---------------------------------------------------------------------------
// Scratch
// ---------------------------------------------------------------------------
__device__ __half g_Xh[(size_t)M_TOT * E_DIM];
__device__ __half g_Wh[4][(size_t)E_DIM * E_DIM];
__device__ __half g_Qh[(size_t)M_TOT * E_DIM];
__device__ __half g_Kh[(size_t)M_TOT * E_DIM];
__device__ __half g_Vh[(size_t)M_TOT * E_DIM];
__device__ __half g_Yh[(size_t)M_TOT * E_DIM];

// ---------------------------------------------------------------------------
// Helpers
// ---------------------------------------------------------------------------
__device__ __forceinline__ void cp16(void* dst_smem, const void* src_gmem) {
    uint32_t d = (uint32_t)__cvta_generic_to_shared(dst_smem);
    asm volatile("cp.async.cg.shared.global [%0], [%1], 16;\n" :: "r"(d), "l"(src_gmem));
}
__device__ __forceinline__ void ldsm_x4(uint32_t& r0, uint32_t& r1,
                                        uint32_t& r2, uint32_t& r3, uint32_t addr) {
    asm volatile("ldmatrix.sync.aligned.m8n8.x4.shared.b16 {%0,%1,%2,%3}, [%4];"
        : "=r"(r0), "=r"(r1), "=r"(r2), "=r"(r3) : "r"(addr));
}
__device__ __forceinline__ void mma_f16(float c[4],
                                        uint32_t a0, uint32_t a1, uint32_t a2, uint32_t a3,
                                        uint32_t b0, uint32_t b1) {
    asm volatile(
        "mma.sync.aligned.m16n8k16.row.col.f32.f16.f16.f32 "
        "{%0,%1,%2,%3}, {%4,%5,%6,%7}, {%8,%9}, {%0,%1,%2,%3};\n"
        : "+f"(c[0]), "+f"(c[1]), "+f"(c[2]), "+f"(c[3])
        : "r"(a0), "r"(a1), "r"(a2), "r"(a3), "r"(b0), "r"(b1));
}

// ---------------------------------------------------------------------------
// fp16 tensor-core GEMM: C[M,N] = A[M,K] @ B[N,K]^T + bias[N]
// 256 threads = 8 warps (2 warp_m x 4 warp_n), warp tile 64x64.
// 2-stage cp.async pipeline (BK=128) + ks-level fragment double buffering.
// ---------------------------------------------------------------------------
template <typename OutT>
__global__ __launch_bounds__(256, 1)
void hgemm_bias_kernel(const __half* __restrict__ A,
                       const __half* __restrict__ B,
                       const float* __restrict__ bias,
                       OutT* __restrict__ C,
                       int M, int N, int K)
{
    extern __shared__ __align__(128) __half smem[];
    const uint32_t smem_u32 = (uint32_t)__cvta_generic_to_shared(smem);

    const int tid    = threadIdx.x;
    const int lane   = tid & 31;
    const int warpId = tid >> 5;
    const int warp_m = warpId & 1;    // 64-row slab
    const int warp_n = warpId >> 1;   // 64-col slab (0..3)

    const int blockN = blockIdx.x * BN;
    const int blockM = blockIdx.y * BM;

    const __half* Ab = A + (size_t)blockM * K;
    const __half* Bb = B + (size_t)blockN * K;

    float acc[4][8][4];
#pragma unroll
    for (int mt = 0; mt < 4; mt++)
#pragma unroll
        for (int nt = 0; nt < 8; nt++)
#pragma unroll
            for (int c = 0; c < 4; c++)
                acc[mt][nt][c] = 0.0f;

    // staging: 16 chunks(16B) per row. A: 2048 chunks (8/thr), B: 4096 (16/thr)
    auto load_stage = [&](int st, int slot) {
        const int k0 = st * BKH;
        __half* As = smem + slot * STG_H;
        __half* Bs = As + A_H;
#pragma unroll
        for (int i = 0; i < 8; i++) {
            int idx = tid + i * 256;
            int row = idx >> 4, c = idx & 15;
            cp16(As + row * LDH + c * 8, Ab + (size_t)row * K + k0 + c * 8);
        }
#pragma unroll
        for (int i = 0; i < 16; i++) {
            int idx = tid + i * 256;
            int row = idx >> 4, c = idx & 15;
            cp16(Bs + row * LDH + c * 8, Bb + (size_t)row * K + k0 + c * 8);
        }
        asm volatile("cp.async.commit_group;\n");
    };

    load_stage(0, 0);
    load_stage(1, 1);

    // ldmatrix per-lane base offsets (halves)
    const int aBase = (warp_m * 64 + (lane & 15)) * LDH + (lane >> 4) * 8;
    const int bBase = (warp_n * 64 + (lane & 7) + ((lane >> 4) * 8)) * LDH
                    + ((lane >> 3) & 1) * 8;

    uint32_t af[2][4][4];
    uint32_t bf[2][8][2];

    for (int it = 0; it < NSTG; it++) {
        if (it + 1 < NSTG) asm volatile("cp.async.wait_group 1;\n");
        else               asm volatile("cp.async.wait_group 0;\n");
        __syncthreads();

        const uint32_t As_u = smem_u32 + ((it & 1) * STG_H) * 2;
        const uint32_t Bs_u = As_u + A_H * 2;

        // prefetch fragments for ks=0
#pragma unroll
        for (int mt = 0; mt < 4; mt++)
            ldsm_x4(af[0][mt][0], af[0][mt][1], af[0][mt][2], af[0][mt][3],
                    As_u + (aBase + mt * 16 * LDH) * 2);
#pragma unroll
        for (int p = 0; p < 4; p++)
            ldsm_x4(bf[0][2 * p][0], bf[0][2 * p][1],
                    bf[0][2 * p + 1][0], bf[0][2 * p + 1][1],
                    Bs_u + (bBase + p * 16 * LDH) * 2);

#pragma unroll
        for (int ks = 0; ks < BKH / 16; ks++) {
            const int cur = ks & 1;
            const int nxt = cur ^ 1;
            if (ks + 1 < BKH / 16) {
#pragma unroll
                for (int mt = 0; mt < 4; mt++)
                    ldsm_x4(af[nxt][mt][0], af[nxt][mt][1], af[nxt][mt][2], af[nxt][mt][3],
                            As_u + (aBase + mt * 16 * LDH + (ks + 1) * 16) * 2);
#pragma unroll
                for (int p = 0; p < 4; p++)
                    ldsm_x4(bf[nxt][2 * p][0], bf[nxt][2 * p][1],
                            bf[nxt][2 * p + 1][0], bf[nxt][2 * p + 1][1],
                            Bs_u + (bBase + p * 16 * LDH + (ks + 1) * 16) * 2);
            }
#pragma unroll
            for (int mt = 0; mt < 4; mt++)
#pragma unroll
                for (int nt = 0; nt < 8; nt++)
                    mma_f16(acc[mt][nt],
                            af[cur][mt][0], af[cur][mt][1], af[cur][mt][2], af[cur][mt][3],
                            bf[cur][nt][0], bf[cur][nt][1]);
        }

        __syncthreads();   // all warps done reading this slot
        if (it + 2 < NSTG) load_stage(it + 2, it & 1);
    }

    // ---- epilogue ----
    const int colBase = blockN + warp_n * 64 + (lane & 3) * 2;
    const int rowBase = blockM + warp_m * 64 + (lane >> 2);
#pragma unroll
    for (int nt = 0; nt < 8; nt++) {
        const int col = colBase + nt * 8;
        const float b0 = bias[col], b1 = bias[col + 1];
#pragma unroll
        for (int mt = 0; mt < 4; mt++) {
            OutT* p0 = C + (size_t)(rowBase + mt * 16) * N + col;
            OutT* p1 = C + (size_t)(rowBase + mt * 16 + 8) * N + col;
            if constexpr (sizeof(OutT) == 4) {
                *reinterpret_cast<float2*>(p0) =
                    make_float2(acc[mt][nt][0] + b0, acc[mt][nt][1] + b1);
                *reinterpret_cast<float2*>(p1) =
                    make_float2(acc[mt][nt][2] + b0, acc[mt][nt][3] + b1);
            } else {
                __half2 h0 = __floats2half2_rn(acc[mt][nt][0] + b0, acc[mt][nt][1] + b1);
                __half2 h1 = __floats2half2_rn(acc[mt][nt][2] + b0, acc[mt][nt][3] + b1);
                *reinterpret_cast<__half2*>(p0) = h0;
                *reinterpret_cast<__half2*>(p1) = h1;
            }
        }
    }
}

// ---------------------------------------------------------------------------
// f32 -> f16 conversion: x (single pointer)
// ---------------------------------------------------------------------------
__global__ __launch_bounds__(256)
void f2h_kernel(const float4* __restrict__ in, uint2* __restrict__ out, int n4)
{
    for (int i = blockIdx.x * blockDim.x + threadIdx.x; i < n4;
         i += gridDim.x * blockDim.x) {
        float4 v = in[i];
        __half2 h0 = __floats2half2_rn(v.x, v.y);
        __half2 h1 = __floats2half2_rn(v.z, v.w);
        uint2 o;
        o.x = *reinterpret_cast<uint32_t*>(&h0);
        o.y = *reinterpret_cast<uint32_t*>(&h1);
        out[i] = o;
    }
}

// all 4 weight matrices in one launch (dst contiguous in g_Wh)
__global__ __launch_bounds__(256)
void f2h_w_kernel(const float4* __restrict__ w0, const float4* __restrict__ w1,
                  const float4* __restrict__ w2, const float4* __restrict__ w3,
                  uint2* __restrict__ out, int wn4)
{
    const int total = 4 * wn4;
    for (int i = blockIdx.x * blockDim.x + threadIdx.x; i < total;
         i += gridDim.x * blockDim.x) {
        const int j = i / wn4;
        const int r = i - j * wn4;
        const float4* src = (j == 0) ? w0 : (j == 1) ? w1 : (j == 2) ? w2 : w3;
        float4 v = src[r];
        __half2 h0 = __floats2half2_rn(v.x, v.y);
        __half2 h1 = __floats2half2_rn(v.z, v.w);
        uint2 o;
        o.x = *reinterpret_cast<uint32_t*>(&h0);
        o.y = *reinterpret_cast<uint32_t*>(&h1);
        out[i] = o;
    }
}

// ---------------------------------------------------------------------------
// Head-axis attention per token (faithful "buggy" einsum), fp16 in/out,
// fp32 accumulation, reshape scramble fused into the store.
// 2 tokens per warp (MLP x2), 128 threads -> 8 tokens per block.
// ---------------------------------------------------------------------------
__device__ __forceinline__ float dot8h(uint4 a, uint4 b) {
    const __half2* ah = reinterpret_cast<const __half2*>(&a);
    const __half2* bh = reinterpret_cast<const __half2*>(&b);
    float s = 0.0f;
#pragma unroll
    for (int t = 0; t < 4; t++) {
        float2 fa = __half22float2(ah[t]);
        float2 fb = __half22float2(bh[t]);
        s += fa.x * fb.x + fa.y * fb.y;
    }
    return s;
}

__global__ __launch_bounds__(128)
void attn_kernel(const __half* __restrict__ Q,
                 const __half* __restrict__ K,
                 const __half* __restrict__ V,
                 __half* __restrict__ Y)
{
    __shared__ uint4 sQ[8][E_DIM / 8];
    __shared__ uint4 sK[8][E_DIM / 8];
    __shared__ uint4 sV[8][E_DIM / 8];

    const int w    = threadIdx.x >> 5;
    const int lane = threadIdx.x & 31;
    const int tok0 = blockIdx.x * 8 + w * 2;

    // prefetch both tokens' Q/K/V (24 independent uint4 loads in flight)
#pragma unroll
    for (int tk = 0; tk < 2; tk++) {
        const int token = tok0 + tk;
        const uint4* Q4 = reinterpret_cast<const uint4*>(Q + (size_t)token * E_DIM);
        const uint4* K4 = reinterpret_cast<const uint4*>(K + (size_t)token * E_DIM);
        const uint4* V4 = reinterpret_cast<const uint4*>(V + (size_t)token * E_DIM);
#pragma unroll
        for (int c = 0; c < 4; c++) {
            sQ[w * 2 + tk][lane + 32 * c] = Q4[lane + 32 * c];
            sK[w * 2 + tk][lane + 32 * c] = K4[lane + 32 * c];
            sV[w * 2 + tk][lane + 32 * c] = V4[lane + 32 * c];
        }
    }
    __syncwarp();

    const int i    = lane >> 1;
    const int half = lane & 1;

#pragma unroll 1
    for (int tk = 0; tk < 2; tk++) {
        const int token = tok0 + tk;
        const int sw = w * 2 + tk;

        uint4 q[8];
#pragma unroll
        for (int c = 0; c < 8; c++) q[c] = sQ[sw][i * 8 + c];

        float e[8];
#pragma unroll
        for (int jj = 0; jj < 8; jj++) {
            const int j = half * 8 + jj;
            float dot = 0.0f;
#pragma unroll
            for (int c = 0; c < 8; c++)
                dot += dot8h(q[c], sK[sw][j * 8 + c]);
            e[jj] = dot * 0.03125f;   // 1/sqrt(1024)
        }

        float mx = e[0];
#pragma unroll
        for (int jj = 1; jj < 8; jj++) mx = fmaxf(mx, e[jj]);
        mx = fmaxf(mx, __shfl_xor_sync(0xffffffffu, mx, 1));

        float p[8], sum = 0.0f;
#pragma unroll
        for (int jj = 0; jj < 8; jj++) {
            p[jj] = __expf(e[jj] - mx);
            sum += p[jj];
        }
        sum += __shfl_xor_sync(0xffffffffu, sum, 1);
        const float inv = 1.0f / sum;

        float pj[16];
#pragma unroll
        for (int jj = 0; jj < 8; jj++) {
            float mine  = p[jj] * inv;
            float other = __shfl_xor_sync(0xffffffffu, mine, 1);
            pj[half * 8 + jj]       = mine;
            pj[(half ^ 1) * 8 + jj] = other;
        }

        const int n = token / S_LEN;
        const int s = token % S_LEN;
        __half* Yrow = Y + ((size_t)(n * S_LEN + i * 512 + (s >> 4)) * E_DIM)
                         + ((s & 15) * 64) + half * 32;

#pragma unroll
        for (int d8 = 0; d8 < 4; d8++) {
            float acc[8];
#pragma unroll
            for (int t = 0; t < 8; t++) acc[t] = 0.0f;
#pragma unroll
            for (int j = 0; j < 16; j++) {
                uint4 v = sV[sw][j * 8 + half * 4 + d8];
                const __half2* vh = reinterpret_cast<const __half2*>(&v);
#pragma unroll
                for (int t = 0; t < 4; t++) {
                    float2 fv = __half22float2(vh[t]);
                    acc[2 * t]     += pj[j] * fv.x;
                    acc[2 * t + 1] += pj[j] * fv.y;
                }
            }
            uint4 o;
            __half2 h0 = __floats2half2_rn(acc[0], acc[1]);
            __half2 h1 = __floats2half2_rn(acc[2], acc[3]);
            __half2 h2 = __floats2half2_rn(acc[4], acc[5]);
            __half2 h3 = __floats2half2_rn(acc[6], acc[7]);
            o.x = *reinterpret_cast<uint32_t*>(&h0);
            o.y = *reinterpret_cast<uint32_t*>(&h1);
            o.z = *reinterpret_cast<uint32_t*>(&h2);
            o.w = *reinterpret_cast<uint32_t*>(&h3);
            *reinterpret_cast<uint4*>(Yrow + d8 * 8) = o;
        }
    }
}

// ---------------------------------------------------------------------------
// Launch
// ---------------------------------------------------------------------------
extern "C" void kernel_launch(void* const* d_in, const int* in_sizes, int n_in,
                              void* d_out, int out_size)
{
    const float* x  = (const float*)d_in[0];
    const float* Ws[4] = { (const float*)d_in[1], (const float*)d_in[2],
                           (const float*)d_in[3], (const float*)d_in[4] };
    const float* bq = (const float*)d_in[5];
    const float* bk = (const float*)d_in[6];
    const float* bv = (const float*)d_in[7];
    const float* bo = (const float*)d_in[8];
    float* out = (float*)d_out;

    __half *Xh, *Wh, *Qh, *Kh, *Vh, *Yh;
    cudaGetSymbolAddress((void**)&Xh, g_Xh);
    cudaGetSymbolAddress((void**)&Wh, g_Wh);
    cudaGetSymbolAddress((void**)&Qh, g_Qh);
    cudaGetSymbolAddress((void**)&Kh, g_Kh);
    cudaGetSymbolAddress((void**)&Vh, g_Vh);
    cudaGetSymbolAddress((void**)&Yh, g_Yh);

    static bool attr_set = false;
    if (!attr_set) {
        cudaFuncSetAttribute(hgemm_bias_kernel<__half>,
                             cudaFuncAttributeMaxDynamicSharedMemorySize, SMEM_BYTES);
        cudaFuncSetAttribute(hgemm_bias_kernel<float>,
                             cudaFuncAttributeMaxDynamicSharedMemorySize, SMEM_BYTES);
        attr_set = true;
    }

    // 1) convert operands to fp16 (2 launches)
    const int xn4 = (M_TOT * E_DIM) / 4;
    const int wn4 = (E_DIM * E_DIM) / 4;
    f2h_kernel<<<2048, 256>>>((const float4*)x, (uint2*)Xh, xn4);
    f2h_w_kernel<<<1024, 256>>>((const float4*)Ws[0], (const float4*)Ws[1],
                                (const float4*)Ws[2], (const float4*)Ws[3],
                                (uint2*)Wh, wn4);

    // 2) Q/K/V projections (fp16 outputs)
    dim3 gblock(256);
    dim3 ggrid(E_DIM / BN, M_TOT / BM);
    hgemm_bias_kernel<__half><<<ggrid, gblock, SMEM_BYTES>>>(
        Xh, Wh + 0 * (size_t)E_DIM * E_DIM, bq, Qh, M_TOT, E_DIM, E_DIM);
    hgemm_bias_kernel<__half><<<ggrid, gblock, SMEM_BYTES>>>(
        Xh, Wh + 1 * (size_t)E_DIM * E_DIM, bk, Kh, M_TOT, E_DIM, E_DIM);
    hgemm_bias_kernel<__half><<<ggrid, gblock, SMEM_BYTES>>>(
        Xh, Wh + 2 * (size_t)E_DIM * E_DIM, bv, Vh, M_TOT, E_DIM, E_DIM);

    // 3) head-axis attention + scramble (fp16 in/out), 8 tokens/block
    attn_kernel<<<M_TOT / 8, 128>>>(Qh, Kh, Vh, Yh);

    // 4) output projection (fp32 out)
    hgemm_bias_kernel<float><<<ggrid, gblock, SMEM_BYTES>>>(
        Yh, Wh + 3 * (size_t)E_DIM * E_DIM, bo, out, M_TOT, E_DIM, E_DIM);
}

// round 10
// speedup vs baseline: 1.0708x; 1.0708x over previous
#include <cuda_runtime.h>
#include <cuda_fp16.h>
#include <cstdint>

// ---------------------------------------------------------------------------
// Problem constants
// ---------------------------------------------------------------------------
#define NB     4
#define S_LEN  8192
#define E_DIM  1024
#define M_TOT  (NB * S_LEN)   // 32768

// ---------------------------------------------------------------------------
// GEMM tiling: block 128x128, warp tile 64x32, BK=64 halves, 3-stage pipeline
// 2 CTAs/SM (register-limited design: ~115 regs/thread)
// ---------------------------------------------------------------------------
#define BM 128
#define BN 128
#define BKH 64                     // K per stage in halves (128 B rows)
#define LDH 72                     // padded smem row stride (halves)
#define A_H (BM * LDH)             // 9216 halves
#define B_H (BN * LDH)             // 9216 halves
#define STG_H (A_H + B_H)          // 18432 halves / stage
#define NSTAGE 3
#define SMEM_BYTES (NSTAGE * STG_H * 2)   // 110592 B -> 2 CTAs/SM
#define NSTG (E_DIM / BKH)         // 16 k-stages

// ---------------------------------------------------------------------------
// Scratch
// ---------------------------------------------------------------------------
__device__ __half g_Xh[(size_t)M_TOT * E_DIM];
__device__ __half g_Wh[4][(size_t)E_DIM * E_DIM];
__device__ __half g_Qh[(size_t)M_TOT * E_DIM];
__device__ __half g_Kh[(size_t)M_TOT * E_DIM];
__device__ __half g_Vh[(size_t)M_TOT * E_DIM];
__device__ __half g_Yh[(size_t)M_TOT * E_DIM];

// ---------------------------------------------------------------------------
// Helpers
// ---------------------------------------------------------------------------
__device__ __forceinline__ void cp16(void* dst_smem, const void* src_gmem) {
    uint32_t d = (uint32_t)__cvta_generic_to_shared(dst_smem);
    asm volatile("cp.async.cg.shared.global [%0], [%1], 16;\n" :: "r"(d), "l"(src_gmem));
}
__device__ __forceinline__ void ldsm_x4(uint32_t& r0, uint32_t& r1,
                                        uint32_t& r2, uint32_t& r3, uint32_t addr) {
    asm volatile("ldmatrix.sync.aligned.m8n8.x4.shared.b16 {%0,%1,%2,%3}, [%4];"
        : "=r"(r0), "=r"(r1), "=r"(r2), "=r"(r3) : "r"(addr));
}
__device__ __forceinline__ void mma_f16(float c[4],
                                        uint32_t a0, uint32_t a1, uint32_t a2, uint32_t a3,
                                        uint32_t b0, uint32_t b1) {
    asm volatile(
        "mma.sync.aligned.m16n8k16.row.col.f32.f16.f16.f32 "
        "{%0,%1,%2,%3}, {%4,%5,%6,%7}, {%8,%9}, {%0,%1,%2,%3};\n"
        : "+f"(c[0]), "+f"(c[1]), "+f"(c[2]), "+f"(c[3])
        : "r"(a0), "r"(a1), "r"(a2), "r"(a3), "r"(b0), "r"(b1));
}

// ---------------------------------------------------------------------------
// fp16 tensor-core GEMM: C[M,N] = A[M,K] @ B[N,K]^T + bias[N]
// 256 threads = 8 warps (2 warp_m x 4 warp_n), warp tile 64x32, 2 CTAs/SM.
// ---------------------------------------------------------------------------
template <typename OutT>
__global__ __launch_bounds__(256, 2)
void hgemm_bias_kernel(const __half* __restrict__ A,
                       const __half* __restrict__ B,
                       const float* __restrict__ bias,
                       OutT* __restrict__ C,
                       int M, int N, int K)
{
    extern __shared__ __align__(128) __half smem[];
    const uint32_t smem_u32 = (uint32_t)__cvta_generic_to_shared(smem);

    const int tid    = threadIdx.x;
    const int lane   = tid & 31;
    const int warpId = tid >> 5;
    const int warp_m = warpId & 1;    // 64-row slab
    const int warp_n = warpId >> 1;   // 32-col slab (0..3)

    const int blockN = blockIdx.x * BN;
    const int blockM = blockIdx.y * BM;

    const __half* Ab = A + (size_t)blockM * K;
    const __half* Bb = B + (size_t)blockN * K;

    float acc[4][4][4];
#pragma unroll
    for (int mt = 0; mt < 4; mt++)
#pragma unroll
        for (int nt = 0; nt < 4; nt++)
#pragma unroll
            for (int c = 0; c < 4; c++)
                acc[mt][nt][c] = 0.0f;

    // staging: 8 chunks(16B) per row; A: 1024 chunks (4/thr), B: same
    auto load_stage = [&](int st, int slot) {
        const int k0 = st * BKH;
        __half* As = smem + slot * STG_H;
        __half* Bs = As + A_H;
#pragma unroll
        for (int i = 0; i < 4; i++) {
            int idx = tid + i * 256;
            int row = idx >> 3, c = idx & 7;
            cp16(As + row * LDH + c * 8, Ab + (size_t)row * K + k0 + c * 8);
        }
#pragma unroll
        for (int i = 0; i < 4; i++) {
            int idx = tid + i * 256;
            int row = idx >> 3, c = idx & 7;
            cp16(Bs + row * LDH + c * 8, Bb + (size_t)row * K + k0 + c * 8);
        }
        asm volatile("cp.async.commit_group;\n");
    };

    load_stage(0, 0);
    load_stage(1, 1);

    // ldmatrix per-lane base offsets (halves)
    const int aBase = (warp_m * 64 + (lane & 15)) * LDH + (lane >> 4) * 8;
    const int bBase = (warp_n * 32 + (lane & 7) + ((lane >> 4) * 8)) * LDH
                    + ((lane >> 3) & 1) * 8;

    int cs = 0, ls = 2;
    for (int it = 0; it < NSTG; it++) {
        if (it + 2 < NSTG) asm volatile("cp.async.wait_group 1;\n");
        else               asm volatile("cp.async.wait_group 0;\n");
        __syncthreads();

        if (it + 2 < NSTG) load_stage(it + 2, ls);

        const uint32_t As_u = smem_u32 + (cs * STG_H) * 2;
        const uint32_t Bs_u = As_u + A_H * 2;

#pragma unroll
        for (int ks = 0; ks < BKH / 16; ks++) {
            uint32_t af[4][4];
#pragma unroll
            for (int mt = 0; mt < 4; mt++)
                ldsm_x4(af[mt][0], af[mt][1], af[mt][2], af[mt][3],
                        As_u + (aBase + mt * 16 * LDH + ks * 16) * 2);

            uint32_t bf[4][2];
#pragma unroll
            for (int p = 0; p < 2; p++)
                ldsm_x4(bf[2 * p][0], bf[2 * p][1], bf[2 * p + 1][0], bf[2 * p + 1][1],
                        Bs_u + (bBase + p * 16 * LDH + ks * 16) * 2);

#pragma unroll
            for (int mt = 0; mt < 4; mt++)
#pragma unroll
                for (int nt = 0; nt < 4; nt++)
                    mma_f16(acc[mt][nt], af[mt][0], af[mt][1], af[mt][2], af[mt][3],
                            bf[nt][0], bf[nt][1]);
        }

        cs = (cs == NSTAGE - 1) ? 0 : cs + 1;
        ls = (ls == NSTAGE - 1) ? 0 : ls + 1;
    }

    // ---- epilogue ----
    const int colBase = blockN + warp_n * 32 + (lane & 3) * 2;
    const int rowBase = blockM + warp_m * 64 + (lane >> 2);
#pragma unroll
    for (int nt = 0; nt < 4; nt++) {
        const int col = colBase + nt * 8;
        const float b0 = bias[col], b1 = bias[col + 1];
#pragma unroll
        for (int mt = 0; mt < 4; mt++) {
            OutT* p0 = C + (size_t)(rowBase + mt * 16) * N + col;
            OutT* p1 = C + (size_t)(rowBase + mt * 16 + 8) * N + col;
            if constexpr (sizeof(OutT) == 4) {
                *reinterpret_cast<float2*>(p0) =
                    make_float2(acc[mt][nt][0] + b0, acc[mt][nt][1] + b1);
                *reinterpret_cast<float2*>(p1) =
                    make_float2(acc[mt][nt][2] + b0, acc[mt][nt][3] + b1);
            } else {
                __half2 h0 = __floats2half2_rn(acc[mt][nt][0] + b0, acc[mt][nt][1] + b1);
                __half2 h1 = __floats2half2_rn(acc[mt][nt][2] + b0, acc[mt][nt][3] + b1);
                *reinterpret_cast<__half2*>(p0) = h0;
                *reinterpret_cast<__half2*>(p1) = h1;
            }
        }
    }
}

// ---------------------------------------------------------------------------
// f32 -> f16 conversion: x (single pointer)
// ---------------------------------------------------------------------------
__global__ __launch_bounds__(256)
void f2h_kernel(const float4* __restrict__ in, uint2* __restrict__ out, int n4)
{
    for (int i = blockIdx.x * blockDim.x + threadIdx.x; i < n4;
         i += gridDim.x * blockDim.x) {
        float4 v = in[i];
        __half2 h0 = __floats2half2_rn(v.x, v.y);
        __half2 h1 = __floats2half2_rn(v.z, v.w);
        uint2 o;
        o.x = *reinterpret_cast<uint32_t*>(&h0);
        o.y = *reinterpret_cast<uint32_t*>(&h1);
        out[i] = o;
    }
}

// all 4 weight matrices in one launch (dst contiguous in g_Wh)
__global__ __launch_bounds__(256)
void f2h_w_kernel(const float4* __restrict__ w0, const float4* __restrict__ w1,
                  const float4* __restrict__ w2, const float4* __restrict__ w3,
                  uint2* __restrict__ out, int wn4)
{
    const int total = 4 * wn4;
    for (int i = blockIdx.x * blockDim.x + threadIdx.x; i < total;
         i += gridDim.x * blockDim.x) {
        const int j = i / wn4;
        const int r = i - j * wn4;
        const float4* src = (j == 0) ? w0 : (j == 1) ? w1 : (j == 2) ? w2 : w3;
        float4 v = src[r];
        __half2 h0 = __floats2half2_rn(v.x, v.y);
        __half2 h1 = __floats2half2_rn(v.z, v.w);
        uint2 o;
        o.x = *reinterpret_cast<uint32_t*>(&h0);
        o.y = *reinterpret_cast<uint32_t*>(&h1);
        out[i] = o;
    }
}

// ---------------------------------------------------------------------------
// Head-axis attention per token (faithful "buggy" einsum), fp16 in/out,
// fp32 accumulation, reshape scramble fused into the store.
// 2 tokens per warp, 128 threads -> 8 tokens per block.
// ---------------------------------------------------------------------------
__device__ __forceinline__ float dot8h(uint4 a, uint4 b) {
    const __half2* ah = reinterpret_cast<const __half2*>(&a);
    const __half2* bh = reinterpret_cast<const __half2*>(&b);
    float s = 0.0f;
#pragma unroll
    for (int t = 0; t < 4; t++) {
        float2 fa = __half22float2(ah[t]);
        float2 fb = __half22float2(bh[t]);
        s += fa.x * fb.x + fa.y * fb.y;
    }
    return s;
}

__global__ __launch_bounds__(128)
void attn_kernel(const __half* __restrict__ Q,
                 const __half* __restrict__ K,
                 const __half* __restrict__ V,
                 __half* __restrict__ Y)
{
    __shared__ uint4 sQ[8][E_DIM / 8];
    __shared__ uint4 sK[8][E_DIM / 8];
    __shared__ uint4 sV[8][E_DIM / 8];

    const int w    = threadIdx.x >> 5;
    const int lane = threadIdx.x & 31;
    const int tok0 = blockIdx.x * 8 + w * 2;

#pragma unroll
    for (int tk = 0; tk < 2; tk++) {
        const int token = tok0 + tk;
        const uint4* Q4 = reinterpret_cast<const uint4*>(Q + (size_t)token * E_DIM);
        const uint4* K4 = reinterpret_cast<const uint4*>(K + (size_t)token * E_DIM);
        const uint4* V4 = reinterpret_cast<const uint4*>(V + (size_t)token * E_DIM);
#pragma unroll
        for (int c = 0; c < 4; c++) {
            sQ[w * 2 + tk][lane + 32 * c] = Q4[lane + 32 * c];
            sK[w * 2 + tk][lane + 32 * c] = K4[lane + 32 * c];
            sV[w * 2 + tk][lane + 32 * c] = V4[lane + 32 * c];
        }
    }
    __syncwarp();

    const int i    = lane >> 1;
    const int half = lane & 1;

#pragma unroll 1
    for (int tk = 0; tk < 2; tk++) {
        const int token = tok0 + tk;
        const int sw = w * 2 + tk;

        uint4 q[8];
#pragma unroll
        for (int c = 0; c < 8; c++) q[c] = sQ[sw][i * 8 + c];

        float e[8];
#pragma unroll
        for (int jj = 0; jj < 8; jj++) {
            const int j = half * 8 + jj;
            float dot = 0.0f;
#pragma unroll
            for (int c = 0; c < 8; c++)
                dot += dot8h(q[c], sK[sw][j * 8 + c]);
            e[jj] = dot * 0.03125f;   // 1/sqrt(1024)
        }

        float mx = e[0];
#pragma unroll
        for (int jj = 1; jj < 8; jj++) mx = fmaxf(mx, e[jj]);
        mx = fmaxf(mx, __shfl_xor_sync(0xffffffffu, mx, 1));

        float p[8], sum = 0.0f;
#pragma unroll
        for (int jj = 0; jj < 8; jj++) {
            p[jj] = __expf(e[jj] - mx);
            sum += p[jj];
        }
        sum += __shfl_xor_sync(0xffffffffu, sum, 1);
        const float inv = 1.0f / sum;

        float pj[16];
#pragma unroll
        for (int jj = 0; jj < 8; jj++) {
            float mine  = p[jj] * inv;
            float other = __shfl_xor_sync(0xffffffffu, mine, 1);
            pj[half * 8 + jj]       = mine;
            pj[(half ^ 1) * 8 + jj] = other;
        }

        const int n = token / S_LEN;
        const int s = token % S_LEN;
        __half* Yrow = Y + ((size_t)(n * S_LEN + i * 512 + (s >> 4)) * E_DIM)
                         + ((s & 15) * 64) + half * 32;

#pragma unroll
        for (int d8 = 0; d8 < 4; d8++) {
            float acc[8];
#pragma unroll
            for (int t = 0; t < 8; t++) acc[t] = 0.0f;
#pragma unroll
            for (int j = 0; j < 16; j++) {
                uint4 v = sV[sw][j * 8 + half * 4 + d8];
                const __half2* vh = reinterpret_cast<const __half2*>(&v);
#pragma unroll
                for (int t = 0; t < 4; t++) {
                    float2 fv = __half22float2(vh[t]);
                    acc[2 * t]     += pj[j] * fv.x;
                    acc[2 * t + 1] += pj[j] * fv.y;
                }
            }
            uint4 o;
            __half2 h0 = __floats2half2_rn(acc[0], acc[1]);
            __half2 h1 = __floats2half2_rn(acc[2], acc[3]);
            __half2 h2 = __floats2half2_rn(acc[4], acc[5]);
            __half2 h3 = __floats2half2_rn(acc[6], acc[7]);
            o.x = *reinterpret_cast<uint32_t*>(&h0);
            o.y = *reinterpret_cast<uint32_t*>(&h1);
            o.z = *reinterpret_cast<uint32_t*>(&h2);
            o.w = *reinterpret_cast<uint32_t*>(&h3);
            *reinterpret_cast<uint4*>(Yrow + d8 * 8) = o;
        }
    }
}

// ---------------------------------------------------------------------------
// Launch
// ---------------------------------------------------------------------------
extern "C" void kernel_launch(void* const* d_in, const int* in_sizes, int n_in,
                              void* d_out, int out_size)
{
    const float* x  = (const float*)d_in[0];
    const float* Ws[4] = { (const float*)d_in[1], (const float*)d_in[2],
                           (const float*)d_in[3], (const float*)d_in[4] };
    const float* bq = (const float*)d_in[5];
    const float* bk = (const float*)d_in[6];
    const float* bv = (const float*)d_in[7];
    const float* bo = (const float*)d_in[8];
    float* out = (float*)d_out;

    __half *Xh, *Wh, *Qh, *Kh, *Vh, *Yh;
    cudaGetSymbolAddress((void**)&Xh, g_Xh);
    cudaGetSymbolAddress((void**)&Wh, g_Wh);
    cudaGetSymbolAddress((void**)&Qh, g_Qh);
    cudaGetSymbolAddress((void**)&Kh, g_Kh);
    cudaGetSymbolAddress((void**)&Vh, g_Vh);
    cudaGetSymbolAddress((void**)&Yh, g_Yh);

    static bool attr_set = false;
    if (!attr_set) {
        cudaFuncSetAttribute(hgemm_bias_kernel<__half>,
                             cudaFuncAttributeMaxDynamicSharedMemorySize, SMEM_BYTES);
        cudaFuncSetAttribute(hgemm_bias_kernel<float>,
                             cudaFuncAttributeMaxDynamicSharedMemorySize, SMEM_BYTES);
        attr_set = true;
    }

    // 1) convert operands to fp16 (2 launches)
    const int xn4 = (M_TOT * E_DIM) / 4;
    const int wn4 = (E_DIM * E_DIM) / 4;
    f2h_kernel<<<2048, 256>>>((const float4*)x, (uint2*)Xh, xn4);
    f2h_w_kernel<<<1024, 256>>>((const float4*)Ws[0], (const float4*)Ws[1],
                                (const float4*)Ws[2], (const float4*)Ws[3],
                                (uint2*)Wh, wn4);

    // 2) Q/K/V projections (fp16 outputs)
    dim3 gblock(256);
    dim3 ggrid(E_DIM / BN, M_TOT / BM);
    hgemm_bias_kernel<__half><<<ggrid, gblock, SMEM_BYTES>>>(
        Xh, Wh + 0 * (size_t)E_DIM * E_DIM, bq, Qh, M_TOT, E_DIM, E_DIM);
    hgemm_bias_kernel<__half><<<ggrid, gblock, SMEM_BYTES>>>(
        Xh, Wh + 1 * (size_t)E_DIM * E_DIM, bk, Kh, M_TOT, E_DIM, E_DIM);
    hgemm_bias_kernel<__half><<<ggrid, gblock, SMEM_BYTES>>>(
        Xh, Wh + 2 * (size_t)E_DIM * E_DIM, bv, Vh, M_TOT, E_DIM, E_DIM);

    // 3) head-axis attention + scramble (fp16 in/out), 8 tokens/block
    attn_kernel<<<M_TOT / 8, 128>>>(Qh, Kh, Vh, Yh);

    // 4) output projection (fp32 out)
    hgemm_bias_kernel<float><<<ggrid, gblock, SMEM_BYTES>>>(
        Yh, Wh + 3 * (size_t)E_DIM * E_DIM, bo, out, M_TOT, E_DIM, E_DIM);
}

// round 11
// speedup vs baseline: 1.1477x; 1.0718x over previous
#include <cuda_runtime.h>
#include <cuda_fp16.h>
#include <cstdint>

// ---------------------------------------------------------------------------
// Problem constants
// ---------------------------------------------------------------------------
#define NB     4
#define S_LEN  8192
#define E_DIM  1024
#define M_TOT  (NB * S_LEN)   // 32768

// ---------------------------------------------------------------------------
// GEMM tiling: block 128x128, warp tile 64x32, BK=64 halves, 3-stage pipeline
// 2 CTAs/SM (regs ~124/thread)
// ---------------------------------------------------------------------------
#define BM 128
#define BN 128
#define BKH 64
#define LDH 72
#define A_H (BM * LDH)
#define B_H (BN * LDH)
#define STG_H (A_H + B_H)
#define NSTAGE 3
#define SMEM_BYTES (NSTAGE * STG_H * 2)   // 110592 B -> 2 CTAs/SM
#define NSTG (E_DIM / BKH)

// attention smem: per token 3 matrices of 16 rows x 72 halves
#define ALD 72
#define ATOK_H (3 * 16 * ALD)             // 3456 halves / token
#define ATTN_SMEM (8 * ATOK_H * 2)        // 8 tokens/block: 55296 B

// ---------------------------------------------------------------------------
// Scratch
// ---------------------------------------------------------------------------
__device__ __half g_Xh[(size_t)M_TOT * E_DIM];
__device__ __half g_Wh[4][(size_t)E_DIM * E_DIM];
__device__ __half g_Qh[(size_t)M_TOT * E_DIM];
__device__ __half g_Kh[(size_t)M_TOT * E_DIM];
__device__ __half g_Vh[(size_t)M_TOT * E_DIM];
__device__ __half g_Yh[(size_t)M_TOT * E_DIM];

// ---------------------------------------------------------------------------
// Helpers
// ---------------------------------------------------------------------------
__device__ __forceinline__ void cp16(void* dst_smem, const void* src_gmem) {
    uint32_t d = (uint32_t)__cvta_generic_to_shared(dst_smem);
    asm volatile("cp.async.cg.shared.global [%0], [%1], 16;\n" :: "r"(d), "l"(src_gmem));
}
__device__ __forceinline__ void ldsm_x4(uint32_t& r0, uint32_t& r1,
                                        uint32_t& r2, uint32_t& r3, uint32_t addr) {
    asm volatile("ldmatrix.sync.aligned.m8n8.x4.shared.b16 {%0,%1,%2,%3}, [%4];"
        : "=r"(r0), "=r"(r1), "=r"(r2), "=r"(r3) : "r"(addr));
}
__device__ __forceinline__ void ldsm_x4_t(uint32_t& r0, uint32_t& r1,
                                          uint32_t& r2, uint32_t& r3, uint32_t addr) {
    asm volatile("ldmatrix.sync.aligned.m8n8.x4.trans.shared.b16 {%0,%1,%2,%3}, [%4];"
        : "=r"(r0), "=r"(r1), "=r"(r2), "=r"(r3) : "r"(addr));
}
__device__ __forceinline__ void mma_f16(float c[4],
                                        uint32_t a0, uint32_t a1, uint32_t a2, uint32_t a3,
                                        uint32_t b0, uint32_t b1) {
    asm volatile(
        "mma.sync.aligned.m16n8k16.row.col.f32.f16.f16.f32 "
        "{%0,%1,%2,%3}, {%4,%5,%6,%7}, {%8,%9}, {%0,%1,%2,%3};\n"
        : "+f"(c[0]), "+f"(c[1]), "+f"(c[2]), "+f"(c[3])
        : "r"(a0), "r"(a1), "r"(a2), "r"(a3), "r"(b0), "r"(b1));
}
__device__ __forceinline__ uint32_t h2u(__half2 h) {
    return *reinterpret_cast<uint32_t*>(&h);
}

// ---------------------------------------------------------------------------
// fp16 tensor-core GEMM (unchanged from R10): C = A @ B^T + bias
// ---------------------------------------------------------------------------
template <typename OutT>
__global__ __launch_bounds__(256, 2)
void hgemm_bias_kernel(const __half* __restrict__ A,
                       const __half* __restrict__ B,
                       const float* __restrict__ bias,
                       OutT* __restrict__ C,
                       int M, int N, int K)
{
    extern __shared__ __align__(128) __half smem[];
    const uint32_t smem_u32 = (uint32_t)__cvta_generic_to_shared(smem);

    const int tid    = threadIdx.x;
    const int lane   = tid & 31;
    const int warpId = tid >> 5;
    const int warp_m = warpId & 1;
    const int warp_n = warpId >> 1;

    const int blockN = blockIdx.x * BN;
    const int blockM = blockIdx.y * BM;

    const __half* Ab = A + (size_t)blockM * K;
    const __half* Bb = B + (size_t)blockN * K;

    float acc[4][4][4];
#pragma unroll
    for (int mt = 0; mt < 4; mt++)
#pragma unroll
        for (int nt = 0; nt < 4; nt++)
#pragma unroll
            for (int c = 0; c < 4; c++)
                acc[mt][nt][c] = 0.0f;

    auto load_stage = [&](int st, int slot) {
        const int k0 = st * BKH;
        __half* As = smem + slot * STG_H;
        __half* Bs = As + A_H;
#pragma unroll
        for (int i = 0; i < 4; i++) {
            int idx = tid + i * 256;
            int row = idx >> 3, c = idx & 7;
            cp16(As + row * LDH + c * 8, Ab + (size_t)row * K + k0 + c * 8);
        }
#pragma unroll
        for (int i = 0; i < 4; i++) {
            int idx = tid + i * 256;
            int row = idx >> 3, c = idx & 7;
            cp16(Bs + row * LDH + c * 8, Bb + (size_t)row * K + k0 + c * 8);
        }
        asm volatile("cp.async.commit_group;\n");
    };

    load_stage(0, 0);
    load_stage(1, 1);

    const int aBase = (warp_m * 64 + (lane & 15)) * LDH + (lane >> 4) * 8;
    const int bBase = (warp_n * 32 + (lane & 7) + ((lane >> 4) * 8)) * LDH
                    + ((lane >> 3) & 1) * 8;

    int cs = 0, ls = 2;
    for (int it = 0; it < NSTG; it++) {
        if (it + 2 < NSTG) asm volatile("cp.async.wait_group 1;\n");
        else               asm volatile("cp.async.wait_group 0;\n");
        __syncthreads();

        if (it + 2 < NSTG) load_stage(it + 2, ls);

        const uint32_t As_u = smem_u32 + (cs * STG_H) * 2;
        const uint32_t Bs_u = As_u + A_H * 2;

#pragma unroll
        for (int ks = 0; ks < BKH / 16; ks++) {
            uint32_t af[4][4];
#pragma unroll
            for (int mt = 0; mt < 4; mt++)
                ldsm_x4(af[mt][0], af[mt][1], af[mt][2], af[mt][3],
                        As_u + (aBase + mt * 16 * LDH + ks * 16) * 2);

            uint32_t bf[4][2];
#pragma unroll
            for (int p = 0; p < 2; p++)
                ldsm_x4(bf[2 * p][0], bf[2 * p][1], bf[2 * p + 1][0], bf[2 * p + 1][1],
                        Bs_u + (bBase + p * 16 * LDH + ks * 16) * 2);

#pragma unroll
            for (int mt = 0; mt < 4; mt++)
#pragma unroll
                for (int nt = 0; nt < 4; nt++)
                    mma_f16(acc[mt][nt], af[mt][0], af[mt][1], af[mt][2], af[mt][3],
                            bf[nt][0], bf[nt][1]);
        }

        cs = (cs == NSTAGE - 1) ? 0 : cs + 1;
        ls = (ls == NSTAGE - 1) ? 0 : ls + 1;
    }

    const int colBase = blockN + warp_n * 32 + (lane & 3) * 2;
    const int rowBase = blockM + warp_m * 64 + (lane >> 2);
#pragma unroll
    for (int nt = 0; nt < 4; nt++) {
        const int col = colBase + nt * 8;
        const float b0 = bias[col], b1 = bias[col + 1];
#pragma unroll
        for (int mt = 0; mt < 4; mt++) {
            OutT* p0 = C + (size_t)(rowBase + mt * 16) * N + col;
            OutT* p1 = C + (size_t)(rowBase + mt * 16 + 8) * N + col;
            if constexpr (sizeof(OutT) == 4) {
                *reinterpret_cast<float2*>(p0) =
                    make_float2(acc[mt][nt][0] + b0, acc[mt][nt][1] + b1);
                *reinterpret_cast<float2*>(p1) =
                    make_float2(acc[mt][nt][2] + b0, acc[mt][nt][3] + b1);
            } else {
                __half2 h0 = __floats2half2_rn(acc[mt][nt][0] + b0, acc[mt][nt][1] + b1);
                __half2 h1 = __floats2half2_rn(acc[mt][nt][2] + b0, acc[mt][nt][3] + b1);
                *reinterpret_cast<__half2*>(p0) = h0;
                *reinterpret_cast<__half2*>(p1) = h1;
            }
        }
    }
}

// ---------------------------------------------------------------------------
// f32 -> f16 conversions
// ---------------------------------------------------------------------------
__global__ __launch_bounds__(256)
void f2h_kernel(const float4* __restrict__ in, uint2* __restrict__ out, int n4)
{
    for (int i = blockIdx.x * blockDim.x + threadIdx.x; i < n4;
         i += gridDim.x * blockDim.x) {
        float4 v = in[i];
        __half2 h0 = __floats2half2_rn(v.x, v.y);
        __half2 h1 = __floats2half2_rn(v.z, v.w);
        uint2 o;
        o.x = h2u(h0); o.y = h2u(h1);
        out[i] = o;
    }
}

__global__ __launch_bounds__(256)
void f2h_w_kernel(const float4* __restrict__ w0, const float4* __restrict__ w1,
                  const float4* __restrict__ w2, const float4* __restrict__ w3,
                  uint2* __restrict__ out, int wn4)
{
    const int total = 4 * wn4;
    for (int i = blockIdx.x * blockDim.x + threadIdx.x; i < total;
         i += gridDim.x * blockDim.x) {
        const int j = i / wn4;
        const int r = i - j * wn4;
        const float4* src = (j == 0) ? w0 : (j == 1) ? w1 : (j == 2) ? w2 : w3;
        float4 v = src[r];
        __half2 h0 = __floats2half2_rn(v.x, v.y);
        __half2 h1 = __floats2half2_rn(v.z, v.w);
        uint2 o;
        o.x = h2u(h0); o.y = h2u(h1);
        out[i] = o;
    }
}

// ---------------------------------------------------------------------------
// Tensor-core head-axis attention. One warp per token.
//   E(16x16) = Q(16x64) @ K(16x64)^T : 4 k-chunks x 2 n-tiles = 8 MMAs
//   P = softmax(E/32) rows; P-frags repacked from E C-frags (standard identity)
//   O(16x64) = P(16x16) @ V(16x64)  : 4 trans-ldsm x 2 = 8 MMAs
// Reshape scramble fused into half2 stores.
// ---------------------------------------------------------------------------
__global__ __launch_bounds__(256)
void attn_kernel(const __half* __restrict__ Q,
                 const __half* __restrict__ K,
                 const __half* __restrict__ V,
                 __half* __restrict__ Y)
{
    extern __shared__ __align__(16) __half asm_smem[];
    const int w    = threadIdx.x >> 5;
    const int lane = threadIdx.x & 31;
    const int token = blockIdx.x * 8 + w;

    __half* sQ = asm_smem + w * ATOK_H;
    __half* sK = sQ + 16 * ALD;
    __half* sV = sK + 16 * ALD;

    const __half* Qg = Q + (size_t)token * E_DIM;
    const __half* Kg = K + (size_t)token * E_DIM;
    const __half* Vg = V + (size_t)token * E_DIM;

    // stage 16x64 (=128 16B chunks) per matrix into padded smem
#pragma unroll
    for (int it = 0; it < 4; it++) {
        const int idx = it * 32 + lane;      // 0..127
        const int row = idx >> 3, c = idx & 7;
        *reinterpret_cast<uint4*>(sQ + row * ALD + c * 8) =
            *reinterpret_cast<const uint4*>(Qg + idx * 8);
        *reinterpret_cast<uint4*>(sK + row * ALD + c * 8) =
            *reinterpret_cast<const uint4*>(Kg + idx * 8);
        *reinterpret_cast<uint4*>(sV + row * ALD + c * 8) =
            *reinterpret_cast<const uint4*>(Vg + idx * 8);
    }
    __syncwarp();

    const uint32_t sQu = (uint32_t)__cvta_generic_to_shared(sQ);
    const uint32_t sKu = (uint32_t)__cvta_generic_to_shared(sK);
    const uint32_t sVu = (uint32_t)__cvta_generic_to_shared(sV);

    // ---- energy: E = Q @ K^T, fp32 accum ----
    const uint32_t qBase = sQu + ((lane & 15) * ALD + (lane >> 4) * 8) * 2;
    const uint32_t kBase = sKu + (((lane & 7) + (lane >> 4) * 8) * ALD
                                  + ((lane >> 3) & 1) * 8) * 2;
    float en0[4] = {0.f, 0.f, 0.f, 0.f};
    float en1[4] = {0.f, 0.f, 0.f, 0.f};
#pragma unroll
    for (int kc = 0; kc < 4; kc++) {
        uint32_t a0, a1, a2, a3, b0, b1, b2, b3;
        ldsm_x4(a0, a1, a2, a3, qBase + kc * 32);
        ldsm_x4(b0, b1, b2, b3, kBase + kc * 32);
        mma_f16(en0, a0, a1, a2, a3, b0, b1);
        mma_f16(en1, a0, a1, a2, a3, b2, b3);
    }

    // lane holds rows m=lane>>2 (c0,c1) and m+8 (c2,c3), cols (lane&3)*2 (+8 in en1)
    float rA[4] = {en0[0] * 0.03125f, en0[1] * 0.03125f,
                   en1[0] * 0.03125f, en1[1] * 0.03125f};   // row m
    float rB[4] = {en0[2] * 0.03125f, en0[3] * 0.03125f,
                   en1[2] * 0.03125f, en1[3] * 0.03125f};   // row m+8

    // softmax across 16 cols: quad reduce (lanes share row within quad)
    float mA = fmaxf(fmaxf(rA[0], rA[1]), fmaxf(rA[2], rA[3]));
    float mB = fmaxf(fmaxf(rB[0], rB[1]), fmaxf(rB[2], rB[3]));
    mA = fmaxf(mA, __shfl_xor_sync(0xffffffffu, mA, 1));
    mA = fmaxf(mA, __shfl_xor_sync(0xffffffffu, mA, 2));
    mB = fmaxf(mB, __shfl_xor_sync(0xffffffffu, mB, 1));
    mB = fmaxf(mB, __shfl_xor_sync(0xffffffffu, mB, 2));

    float sA = 0.f, sB = 0.f;
#pragma unroll
    for (int t = 0; t < 4; t++) {
        rA[t] = __expf(rA[t] - mA); sA += rA[t];
        rB[t] = __expf(rB[t] - mB); sB += rB[t];
    }
    sA += __shfl_xor_sync(0xffffffffu, sA, 1);
    sA += __shfl_xor_sync(0xffffffffu, sA, 2);
    sB += __shfl_xor_sync(0xffffffffu, sB, 1);
    sB += __shfl_xor_sync(0xffffffffu, sB, 2);
    const float iA = 1.0f / sA, iB = 1.0f / sB;

    // P fragments (A-operand layout): a0=(m,k),a1=(m+8,k),a2=(m,k+8),a3=(m+8,k+8)
    const uint32_t pa0 = h2u(__floats2half2_rn(rA[0] * iA, rA[1] * iA));
    const uint32_t pa1 = h2u(__floats2half2_rn(rB[0] * iB, rB[1] * iB));
    const uint32_t pa2 = h2u(__floats2half2_rn(rA[2] * iA, rA[3] * iA));
    const uint32_t pa3 = h2u(__floats2half2_rn(rB[2] * iB, rB[3] * iB));

    // ---- O = P @ V ----
    const uint32_t vBase = sVu + (((lane & 7) + ((lane >> 3) & 1) * 8) * ALD
                                  + (lane >> 4) * 8) * 2;
    float o[8][4];
#pragma unroll
    for (int t = 0; t < 8; t++)
#pragma unroll
        for (int c = 0; c < 4; c++) o[t][c] = 0.f;

#pragma unroll
    for (int nt = 0; nt < 4; nt++) {
        uint32_t v0, v1, v2, v3;
        ldsm_x4_t(v0, v1, v2, v3, vBase + nt * 32);
        mma_f16(o[2 * nt],     pa0, pa1, pa2, pa3, v0, v1);
        mma_f16(o[2 * nt + 1], pa0, pa1, pa2, pa3, v2, v3);
    }

    // ---- scatter store with reshape scramble ----
    const int nb = token / S_LEN;
    const int s  = token % S_LEN;
    const int i  = lane >> 2;
    const size_t baseA = ((size_t)(nb * S_LEN + i * 512 + (s >> 4))) * E_DIM
                       + (s & 15) * 64 + (lane & 3) * 2;
    const size_t baseB = ((size_t)(nb * S_LEN + (i + 8) * 512 + (s >> 4))) * E_DIM
                       + (s & 15) * 64 + (lane & 3) * 2;
#pragma unroll
    for (int t = 0; t < 8; t++) {
        *reinterpret_cast<__half2*>(Y + baseA + t * 8) =
            __floats2half2_rn(o[t][0], o[t][1]);
        *reinterpret_cast<__half2*>(Y + baseB + t * 8) =
            __floats2half2_rn(o[t][2], o[t][3]);
    }
}

// ---------------------------------------------------------------------------
// Launch
// ---------------------------------------------------------------------------
extern "C" void kernel_launch(void* const* d_in, const int* in_sizes, int n_in,
                              void* d_out, int out_size)
{
    const float* x  = (const float*)d_in[0];
    const float* Ws[4] = { (const float*)d_in[1], (const float*)d_in[2],
                           (const float*)d_in[3], (const float*)d_in[4] };
    const float* bq = (const float*)d_in[5];
    const float* bk = (const float*)d_in[6];
    const float* bv = (const float*)d_in[7];
    const float* bo = (const float*)d_in[8];
    float* out = (float*)d_out;

    __half *Xh, *Wh, *Qh, *Kh, *Vh, *Yh;
    cudaGetSymbolAddress((void**)&Xh, g_Xh);
    cudaGetSymbolAddress((void**)&Wh, g_Wh);
    cudaGetSymbolAddress((void**)&Qh, g_Qh);
    cudaGetSymbolAddress((void**)&Kh, g_Kh);
    cudaGetSymbolAddress((void**)&Vh, g_Vh);
    cudaGetSymbolAddress((void**)&Yh, g_Yh);

    static bool attr_set = false;
    if (!attr_set) {
        cudaFuncSetAttribute(hgemm_bias_kernel<__half>,
                             cudaFuncAttributeMaxDynamicSharedMemorySize, SMEM_BYTES);
        cudaFuncSetAttribute(hgemm_bias_kernel<float>,
                             cudaFuncAttributeMaxDynamicSharedMemorySize, SMEM_BYTES);
        cudaFuncSetAttribute(attn_kernel,
                             cudaFuncAttributeMaxDynamicSharedMemorySize, ATTN_SMEM);
        attr_set = true;
    }

    // 1) convert operands to fp16
    const int xn4 = (M_TOT * E_DIM) / 4;
    const int wn4 = (E_DIM * E_DIM) / 4;
    f2h_kernel<<<2048, 256>>>((const float4*)x, (uint2*)Xh, xn4);
    f2h_w_kernel<<<1024, 256>>>((const float4*)Ws[0], (const float4*)Ws[1],
                                (const float4*)Ws[2], (const float4*)Ws[3],
                                (uint2*)Wh, wn4);

    // 2) Q/K/V projections (fp16 outputs)
    dim3 gblock(256);
    dim3 ggrid(E_DIM / BN, M_TOT / BM);
    hgemm_bias_kernel<__half><<<ggrid, gblock, SMEM_BYTES>>>(
        Xh, Wh + 0 * (size_t)E_DIM * E_DIM, bq, Qh, M_TOT, E_DIM, E_DIM);
    hgemm_bias_kernel<__half><<<ggrid, gblock, SMEM_BYTES>>>(
        Xh, Wh + 1 * (size_t)E_DIM * E_DIM, bk, Kh, M_TOT, E_DIM, E_DIM);
    hgemm_bias_kernel<__half><<<ggrid, gblock, SMEM_BYTES>>>(
        Xh, Wh + 2 * (size_t)E_DIM * E_DIM, bv, Vh, M_TOT, E_DIM, E_DIM);

    // 3) tensor-core head-axis attention + scramble (8 tokens/block)
    attn_kernel<<<M_TOT / 8, 256, ATTN_SMEM>>>(Qh, Kh, Vh, Yh);

    // 4) output projection (fp32 out)
    hgemm_bias_kernel<float><<<ggrid, gblock, SMEM_BYTES>>>(
        Yh, Wh + 3 * (size_t)E_DIM * E_DIM, bo, out, M_TOT, E_DIM, E_DIM);
}

// round 12
// speedup vs baseline: 1.1612x; 1.0118x over previous
#include <cuda_runtime.h>
#include <cuda_fp16.h>
#include <cstdint>

// ---------------------------------------------------------------------------
// Problem constants
// ---------------------------------------------------------------------------
#define NB     4
#define S_LEN  8192
#define E_DIM  1024
#define M_TOT  (NB * S_LEN)   // 32768
#define N_QKV  3072

// ---------------------------------------------------------------------------
// GEMM tiling: block 128x128, warp tile 64x32, BK=64 halves, 3-stage pipeline
// 2 CTAs/SM (regs ~124/thread)  [R10 validated config — do not touch]
// ---------------------------------------------------------------------------
#define BM 128
#define BN 128
#define BKH 64
#define LDH 72
#define A_H (BM * LDH)
#define B_H (BN * LDH)
#define STG_H (A_H + B_H)
#define NSTAGE 3
#define SMEM_BYTES (NSTAGE * STG_H * 2)   // 110592 B -> 2 CTAs/SM
#define NSTG (E_DIM / BKH)

// attention smem: per token 3 matrices of 16 rows x 72 halves
#define ALD 72
#define ATOK_H (3 * 16 * ALD)
#define ATTN_SMEM (8 * ATOK_H * 2)        // 55296 B

// ---------------------------------------------------------------------------
// Scratch
// ---------------------------------------------------------------------------
__device__ __half g_Xh[(size_t)M_TOT * E_DIM];
__device__ __half g_Wh[4][(size_t)E_DIM * E_DIM];   // Wq,Wk,Wv contiguous = [3072,1024]; Wo after
__device__ __half g_QKVh[(size_t)M_TOT * N_QKV];    // per token: Q|K|V
__device__ __half g_Yh[(size_t)M_TOT * E_DIM];

// ---------------------------------------------------------------------------
// Helpers
// ---------------------------------------------------------------------------
__device__ __forceinline__ void cp16(void* dst_smem, const void* src_gmem) {
    uint32_t d = (uint32_t)__cvta_generic_to_shared(dst_smem);
    asm volatile("cp.async.cg.shared.global [%0], [%1], 16;\n" :: "r"(d), "l"(src_gmem));
}
__device__ __forceinline__ void ldsm_x4(uint32_t& r0, uint32_t& r1,
                                        uint32_t& r2, uint32_t& r3, uint32_t addr) {
    asm volatile("ldmatrix.sync.aligned.m8n8.x4.shared.b16 {%0,%1,%2,%3}, [%4];"
        : "=r"(r0), "=r"(r1), "=r"(r2), "=r"(r3) : "r"(addr));
}
__device__ __forceinline__ void ldsm_x4_t(uint32_t& r0, uint32_t& r1,
                                          uint32_t& r2, uint32_t& r3, uint32_t addr) {
    asm volatile("ldmatrix.sync.aligned.m8n8.x4.trans.shared.b16 {%0,%1,%2,%3}, [%4];"
        : "=r"(r0), "=r"(r1), "=r"(r2), "=r"(r3) : "r"(addr));
}
__device__ __forceinline__ void mma_f16(float c[4],
                                        uint32_t a0, uint32_t a1, uint32_t a2, uint32_t a3,
                                        uint32_t b0, uint32_t b1) {
    asm volatile(
        "mma.sync.aligned.m16n8k16.row.col.f32.f16.f16.f32 "
        "{%0,%1,%2,%3}, {%4,%5,%6,%7}, {%8,%9}, {%0,%1,%2,%3};\n"
        : "+f"(c[0]), "+f"(c[1]), "+f"(c[2]), "+f"(c[3])
        : "r"(a0), "r"(a1), "r"(a2), "r"(a3), "r"(b0), "r"(b1));
}
__device__ __forceinline__ uint32_t h2u(__half2 h) {
    return *reinterpret_cast<uint32_t*>(&h);
}

// ---------------------------------------------------------------------------
// fp16 tensor-core GEMM: C[M, :] = A[M,K] @ B[N,K]^T + bias
// N given implicitly by grid; ldc = C row stride. Bias segmented per 1024
// columns (b0/b1/b2) so one launch covers the fused QKV projection.
// ---------------------------------------------------------------------------
template <typename OutT>
__global__ __launch_bounds__(256, 2)
void hgemm_bias_kernel(const __half* __restrict__ A,
                       const __half* __restrict__ B,
                       const float* __restrict__ b0,
                       const float* __restrict__ b1,
                       const float* __restrict__ b2,
                       OutT* __restrict__ C,
                       int M, int ldc, int K)
{
    extern __shared__ __align__(128) __half smem[];
    const uint32_t smem_u32 = (uint32_t)__cvta_generic_to_shared(smem);

    const int tid    = threadIdx.x;
    const int lane   = tid & 31;
    const int warpId = tid >> 5;
    const int warp_m = warpId & 1;
    const int warp_n = warpId >> 1;

    const int blockN = blockIdx.x * BN;
    const int blockM = blockIdx.y * BM;

    const __half* Ab = A + (size_t)blockM * K;
    const __half* Bb = B + (size_t)blockN * K;

    float acc[4][4][4];
#pragma unroll
    for (int mt = 0; mt < 4; mt++)
#pragma unroll
        for (int nt = 0; nt < 4; nt++)
#pragma unroll
            for (int c = 0; c < 4; c++)
                acc[mt][nt][c] = 0.0f;

    auto load_stage = [&](int st, int slot) {
        const int k0 = st * BKH;
        __half* As = smem + slot * STG_H;
        __half* Bs = As + A_H;
#pragma unroll
        for (int i = 0; i < 4; i++) {
            int idx = tid + i * 256;
            int row = idx >> 3, c = idx & 7;
            cp16(As + row * LDH + c * 8, Ab + (size_t)row * K + k0 + c * 8);
        }
#pragma unroll
        for (int i = 0; i < 4; i++) {
            int idx = tid + i * 256;
            int row = idx >> 3, c = idx & 7;
            cp16(Bs + row * LDH + c * 8, Bb + (size_t)row * K + k0 + c * 8);
        }
        asm volatile("cp.async.commit_group;\n");
    };

    load_stage(0, 0);
    load_stage(1, 1);

    const int aBase = (warp_m * 64 + (lane & 15)) * LDH + (lane >> 4) * 8;
    const int bBase = (warp_n * 32 + (lane & 7) + ((lane >> 4) * 8)) * LDH
                    + ((lane >> 3) & 1) * 8;

    int cs = 0, ls = 2;
    for (int it = 0; it < NSTG; it++) {
        if (it + 2 < NSTG) asm volatile("cp.async.wait_group 1;\n");
        else               asm volatile("cp.async.wait_group 0;\n");
        __syncthreads();

        if (it + 2 < NSTG) load_stage(it + 2, ls);

        const uint32_t As_u = smem_u32 + (cs * STG_H) * 2;
        const uint32_t Bs_u = As_u + A_H * 2;

#pragma unroll
        for (int ks = 0; ks < BKH / 16; ks++) {
            uint32_t af[4][4];
#pragma unroll
            for (int mt = 0; mt < 4; mt++)
                ldsm_x4(af[mt][0], af[mt][1], af[mt][2], af[mt][3],
                        As_u + (aBase + mt * 16 * LDH + ks * 16) * 2);

            uint32_t bf[4][2];
#pragma unroll
            for (int p = 0; p < 2; p++)
                ldsm_x4(bf[2 * p][0], bf[2 * p][1], bf[2 * p + 1][0], bf[2 * p + 1][1],
                        Bs_u + (bBase + p * 16 * LDH + ks * 16) * 2);

#pragma unroll
            for (int mt = 0; mt < 4; mt++)
#pragma unroll
                for (int nt = 0; nt < 4; nt++)
                    mma_f16(acc[mt][nt], af[mt][0], af[mt][1], af[mt][2], af[mt][3],
                            bf[nt][0], bf[nt][1]);
        }

        cs = (cs == NSTAGE - 1) ? 0 : cs + 1;
        ls = (ls == NSTAGE - 1) ? 0 : ls + 1;
    }

    // ---- epilogue: segmented bias, strided C ----
    const int seg = blockN >> 10;
    const float* bias = (seg == 0) ? b0 : (seg == 1) ? b1 : b2;
    const int colSeg  = (blockN & 1023) + warp_n * 32 + (lane & 3) * 2;
    const int colGlb  = blockN + warp_n * 32 + (lane & 3) * 2;
    const int rowBase = blockM + warp_m * 64 + (lane >> 2);
#pragma unroll
    for (int nt = 0; nt < 4; nt++) {
        const float bv0 = bias[colSeg + nt * 8], bv1 = bias[colSeg + nt * 8 + 1];
#pragma unroll
        for (int mt = 0; mt < 4; mt++) {
            OutT* p0 = C + (size_t)(rowBase + mt * 16) * ldc + colGlb + nt * 8;
            OutT* p1 = C + (size_t)(rowBase + mt * 16 + 8) * ldc + colGlb + nt * 8;
            if constexpr (sizeof(OutT) == 4) {
                *reinterpret_cast<float2*>(p0) =
                    make_float2(acc[mt][nt][0] + bv0, acc[mt][nt][1] + bv1);
                *reinterpret_cast<float2*>(p1) =
                    make_float2(acc[mt][nt][2] + bv0, acc[mt][nt][3] + bv1);
            } else {
                *reinterpret_cast<__half2*>(p0) =
                    __floats2half2_rn(acc[mt][nt][0] + bv0, acc[mt][nt][1] + bv1);
                *reinterpret_cast<__half2*>(p1) =
                    __floats2half2_rn(acc[mt][nt][2] + bv0, acc[mt][nt][3] + bv1);
            }
        }
    }
}

// ---------------------------------------------------------------------------
// One-shot f32 -> f16: x followed by all 4 weight matrices
// ---------------------------------------------------------------------------
__global__ __launch_bounds__(256)
void f2h_all_kernel(const float4* __restrict__ x,
                    const float4* __restrict__ w0, const float4* __restrict__ w1,
                    const float4* __restrict__ w2, const float4* __restrict__ w3,
                    uint2* __restrict__ outx, uint2* __restrict__ outw,
                    int xn4, int wn4)
{
    const int total = xn4 + 4 * wn4;
    for (int i = blockIdx.x * blockDim.x + threadIdx.x; i < total;
         i += gridDim.x * blockDim.x) {
        float4 v;
        uint2* dst;
        if (i < xn4) {
            v = x[i];
            dst = outx + i;
        } else {
            const int t = i - xn4;
            const int j = t / wn4;
            const int r = t - j * wn4;
            const float4* src = (j == 0) ? w0 : (j == 1) ? w1 : (j == 2) ? w2 : w3;
            v = src[r];
            dst = outw + t;
        }
        __half2 h0 = __floats2half2_rn(v.x, v.y);
        __half2 h1 = __floats2half2_rn(v.z, v.w);
        uint2 o;
        o.x = h2u(h0); o.y = h2u(h1);
        *dst = o;
    }
}

// ---------------------------------------------------------------------------
// Tensor-core head-axis attention (R11 validated). One warp per token.
// QKV packed per token: Q = row[0:1024], K = [1024:2048], V = [2048:3072].
// ---------------------------------------------------------------------------
__global__ __launch_bounds__(256)
void attn_kernel(const __half* __restrict__ QKV, __half* __restrict__ Y)
{
    extern __shared__ __align__(16) __half asm_smem[];
    const int w    = threadIdx.x >> 5;
    const int lane = threadIdx.x & 31;
    const int token = blockIdx.x * 8 + w;

    __half* sQ = asm_smem + w * ATOK_H;
    __half* sK = sQ + 16 * ALD;
    __half* sV = sK + 16 * ALD;

    const __half* Qg = QKV + (size_t)token * N_QKV;
    const __half* Kg = Qg + E_DIM;
    const __half* Vg = Qg + 2 * E_DIM;

#pragma unroll
    for (int it = 0; it < 4; it++) {
        const int idx = it * 32 + lane;
        const int row = idx >> 3, c = idx & 7;
        *reinterpret_cast<uint4*>(sQ + row * ALD + c * 8) =
            *reinterpret_cast<const uint4*>(Qg + idx * 8);
        *reinterpret_cast<uint4*>(sK + row * ALD + c * 8) =
            *reinterpret_cast<const uint4*>(Kg + idx * 8);
        *reinterpret_cast<uint4*>(sV + row * ALD + c * 8) =
            *reinterpret_cast<const uint4*>(Vg + idx * 8);
    }
    __syncwarp();

    const uint32_t sQu = (uint32_t)__cvta_generic_to_shared(sQ);
    const uint32_t sKu = (uint32_t)__cvta_generic_to_shared(sK);
    const uint32_t sVu = (uint32_t)__cvta_generic_to_shared(sV);

    const uint32_t qBase = sQu + ((lane & 15) * ALD + (lane >> 4) * 8) * 2;
    const uint32_t kBase = sKu + (((lane & 7) + (lane >> 4) * 8) * ALD
                                  + ((lane >> 3) & 1) * 8) * 2;
    float en0[4] = {0.f, 0.f, 0.f, 0.f};
    float en1[4] = {0.f, 0.f, 0.f, 0.f};
#pragma unroll
    for (int kc = 0; kc < 4; kc++) {
        uint32_t a0, a1, a2, a3, b0, b1, b2, b3;
        ldsm_x4(a0, a1, a2, a3, qBase + kc * 32);
        ldsm_x4(b0, b1, b2, b3, kBase + kc * 32);
        mma_f16(en0, a0, a1, a2, a3, b0, b1);
        mma_f16(en1, a0, a1, a2, a3, b2, b3);
    }

    float rA[4] = {en0[0] * 0.03125f, en0[1] * 0.03125f,
                   en1[0] * 0.03125f, en1[1] * 0.03125f};
    float rB[4] = {en0[2] * 0.03125f, en0[3] * 0.03125f,
                   en1[2] * 0.03125f, en1[3] * 0.03125f};

    float mA = fmaxf(fmaxf(rA[0], rA[1]), fmaxf(rA[2], rA[3]));
    float mB = fmaxf(fmaxf(rB[0], rB[1]), fmaxf(rB[2], rB[3]));
    mA = fmaxf(mA, __shfl_xor_sync(0xffffffffu, mA, 1));
    mA = fmaxf(mA, __shfl_xor_sync(0xffffffffu, mA, 2));
    mB = fmaxf(mB, __shfl_xor_sync(0xffffffffu, mB, 1));
    mB = fmaxf(mB, __shfl_xor_sync(0xffffffffu, mB, 2));

    float sA = 0.f, sB = 0.f;
#pragma unroll
    for (int t = 0; t < 4; t++) {
        rA[t] = __expf(rA[t] - mA); sA += rA[t];
        rB[t] = __expf(rB[t] - mB); sB += rB[t];
    }
    sA += __shfl_xor_sync(0xffffffffu, sA, 1);
    sA += __shfl_xor_sync(0xffffffffu, sA, 2);
    sB += __shfl_xor_sync(0xffffffffu, sB, 1);
    sB += __shfl_xor_sync(0xffffffffu, sB, 2);
    const float iA = 1.0f / sA, iB = 1.0f / sB;

    const uint32_t pa0 = h2u(__floats2half2_rn(rA[0] * iA, rA[1] * iA));
    const uint32_t pa1 = h2u(__floats2half2_rn(rB[0] * iB, rB[1] * iB));
    const uint32_t pa2 = h2u(__floats2half2_rn(rA[2] * iA, rA[3] * iA));
    const uint32_t pa3 = h2u(__floats2half2_rn(rB[2] * iB, rB[3] * iB));

    const uint32_t vBase = sVu + (((lane & 7) + ((lane >> 3) & 1) * 8) * ALD
                                  + (lane >> 4) * 8) * 2;
    float o[8][4];
#pragma unroll
    for (int t = 0; t < 8; t++)
#pragma unroll
        for (int c = 0; c < 4; c++) o[t][c] = 0.f;

#pragma unroll
    for (int nt = 0; nt < 4; nt++) {
        uint32_t v0, v1, v2, v3;
        ldsm_x4_t(v0, v1, v2, v3, vBase + nt * 32);
        mma_f16(o[2 * nt],     pa0, pa1, pa2, pa3, v0, v1);
        mma_f16(o[2 * nt + 1], pa0, pa1, pa2, pa3, v2, v3);
    }

    const int nb = token / S_LEN;
    const int s  = token % S_LEN;
    const int i  = lane >> 2;
    const size_t baseA = ((size_t)(nb * S_LEN + i * 512 + (s >> 4))) * E_DIM
                       + (s & 15) * 64 + (lane & 3) * 2;
    const size_t baseB = ((size_t)(nb * S_LEN + (i + 8) * 512 + (s >> 4))) * E_DIM
                       + (s & 15) * 64 + (lane & 3) * 2;
#pragma unroll
    for (int t = 0; t < 8; t++) {
        *reinterpret_cast<__half2*>(Y + baseA + t * 8) =
            __floats2half2_rn(o[t][0], o[t][1]);
        *reinterpret_cast<__half2*>(Y + baseB + t * 8) =
            __floats2half2_rn(o[t][2], o[t][3]);
    }
}

// ---------------------------------------------------------------------------
// Launch: 3 heavy launches total
// ---------------------------------------------------------------------------
extern "C" void kernel_launch(void* const* d_in, const int* in_sizes, int n_in,
                              void* d_out, int out_size)
{
    const float* x  = (const float*)d_in[0];
    const float* Ws[4] = { (const float*)d_in[1], (const float*)d_in[2],
                           (const float*)d_in[3], (const float*)d_in[4] };
    const float* bq = (const float*)d_in[5];
    const float* bk = (const float*)d_in[6];
    const float* bv = (const float*)d_in[7];
    const float* bo = (const float*)d_in[8];
    float* out = (float*)d_out;

    __half *Xh, *Wh, *QKVh, *Yh;
    cudaGetSymbolAddress((void**)&Xh,   g_Xh);
    cudaGetSymbolAddress((void**)&Wh,   g_Wh);
    cudaGetSymbolAddress((void**)&QKVh, g_QKVh);
    cudaGetSymbolAddress((void**)&Yh,   g_Yh);

    static bool attr_set = false;
    if (!attr_set) {
        cudaFuncSetAttribute(hgemm_bias_kernel<__half>,
                             cudaFuncAttributeMaxDynamicSharedMemorySize, SMEM_BYTES);
        cudaFuncSetAttribute(hgemm_bias_kernel<float>,
                             cudaFuncAttributeMaxDynamicSharedMemorySize, SMEM_BYTES);
        cudaFuncSetAttribute(attn_kernel,
                             cudaFuncAttributeMaxDynamicSharedMemorySize, ATTN_SMEM);
        attr_set = true;
    }

    // 1) one-shot fp16 conversion (x + all weights)
    const int xn4 = (M_TOT * E_DIM) / 4;
    const int wn4 = (E_DIM * E_DIM) / 4;
    f2h_all_kernel<<<3072, 256>>>((const float4*)x,
                                  (const float4*)Ws[0], (const float4*)Ws[1],
                                  (const float4*)Ws[2], (const float4*)Ws[3],
                                  (uint2*)Xh, (uint2*)Wh, xn4, wn4);

    // 2) fused Q/K/V projection: [M,1024] @ [3072,1024]^T -> [M,3072] fp16
    dim3 gblock(256);
    dim3 gridQKV(N_QKV / BN, M_TOT / BM);
    hgemm_bias_kernel<__half><<<gridQKV, gblock, SMEM_BYTES>>>(
        Xh, Wh, bq, bk, bv, QKVh, M_TOT, N_QKV, E_DIM);

    // 3) tensor-core head-axis attention + scramble (8 tokens/block)
    attn_kernel<<<M_TOT / 8, 256, ATTN_SMEM>>>(QKVh, Yh);

    // 4) output projection (fp32 out)
    dim3 gridO(E_DIM / BN, M_TOT / BM);
    hgemm_bias_kernel<float><<<gridO, gblock, SMEM_BYTES>>>(
        Yh, Wh + 3 * (size_t)E_DIM * E_DIM, bo, bo, bo, out, M_TOT, E_DIM, E_DIM);
}

// round 13
// speedup vs baseline: 1.2066x; 1.0391x over previous
#include <cuda_runtime.h>
#include <cuda_fp16.h>
#include <cstdint>

// ---------------------------------------------------------------------------
// Problem constants
// ---------------------------------------------------------------------------
#define NB     4
#define S_LEN  8192
#define E_DIM  1024
#define M_TOT  (NB * S_LEN)   // 32768
#define N_QKV  3072

// ---------------------------------------------------------------------------
// GEMM tiling: block 128x128, warp tile 64x32, BK=64 halves, 3-stage pipeline
// 2 CTAs/SM (regs ~124/thread)  [validated config — mainloop math unchanged]
// ---------------------------------------------------------------------------
#define BM 128
#define BN 128
#define BKH 64
#define LDH 72
#define A_H (BM * LDH)
#define B_H (BN * LDH)
#define STG_H (A_H + B_H)
#define NSTAGE 3
#define SMEM_BYTES (NSTAGE * STG_H * 2)   // 110592 B -> 2 CTAs/SM
#define NSTG (E_DIM / BKH)

// attention smem: per token 3 matrices of 16 rows x 72 halves
#define ALD 72
#define ATOK_H (3 * 16 * ALD)
#define ATTN_SMEM (8 * ATOK_H * 2)        // 55296 B

// ---------------------------------------------------------------------------
// Scratch
// ---------------------------------------------------------------------------
__device__ __half g_Xh[(size_t)M_TOT * E_DIM];
__device__ __half g_Wh[4][(size_t)E_DIM * E_DIM];   // Wq,Wk,Wv contiguous; Wo after
__device__ __half g_QKVh[(size_t)M_TOT * N_QKV];    // per token: Q|K|V
__device__ __half g_Yh[(size_t)M_TOT * E_DIM];

// ---------------------------------------------------------------------------
// Helpers
// ---------------------------------------------------------------------------
__device__ __forceinline__ void cp16(void* dst_smem, const void* src_gmem) {
    uint32_t d = (uint32_t)__cvta_generic_to_shared(dst_smem);
    asm volatile("cp.async.cg.shared.global [%0], [%1], 16;\n" :: "r"(d), "l"(src_gmem));
}
__device__ __forceinline__ void ldsm_x4(uint32_t& r0, uint32_t& r1,
                                        uint32_t& r2, uint32_t& r3, uint32_t addr) {
    asm volatile("ldmatrix.sync.aligned.m8n8.x4.shared.b16 {%0,%1,%2,%3}, [%4];"
        : "=r"(r0), "=r"(r1), "=r"(r2), "=r"(r3) : "r"(addr));
}
__device__ __forceinline__ void ldsm_x4_t(uint32_t& r0, uint32_t& r1,
                                          uint32_t& r2, uint32_t& r3, uint32_t addr) {
    asm volatile("ldmatrix.sync.aligned.m8n8.x4.trans.shared.b16 {%0,%1,%2,%3}, [%4];"
        : "=r"(r0), "=r"(r1), "=r"(r2), "=r"(r3) : "r"(addr));
}
__device__ __forceinline__ void mma_f16(float c[4],
                                        uint32_t a0, uint32_t a1, uint32_t a2, uint32_t a3,
                                        uint32_t b0, uint32_t b1) {
    asm volatile(
        "mma.sync.aligned.m16n8k16.row.col.f32.f16.f16.f32 "
        "{%0,%1,%2,%3}, {%4,%5,%6,%7}, {%8,%9}, {%0,%1,%2,%3};\n"
        : "+f"(c[0]), "+f"(c[1]), "+f"(c[2]), "+f"(c[3])
        : "r"(a0), "r"(a1), "r"(a2), "r"(a3), "r"(b0), "r"(b1));
}
__device__ __forceinline__ uint32_t h2u(__half2 h) {
    return *reinterpret_cast<uint32_t*>(&h);
}

// ---------------------------------------------------------------------------
// fp16 tensor-core GEMM: C[M, :] = A[M,K] @ B[N,K]^T + bias (segmented)
// Stage-head reorder: ks=0 LDSM issued BEFORE next-stage cp.async so the
// LDGSTS issue cost hides under LDSM latency instead of preceding it.
// ---------------------------------------------------------------------------
template <typename OutT>
__global__ __launch_bounds__(256, 2)
void hgemm_bias_kernel(const __half* __restrict__ A,
                       const __half* __restrict__ B,
                       const float* __restrict__ b0,
                       const float* __restrict__ b1,
                       const float* __restrict__ b2,
                       OutT* __restrict__ C,
                       int M, int ldc, int K)
{
    extern __shared__ __align__(128) __half smem[];
    const uint32_t smem_u32 = (uint32_t)__cvta_generic_to_shared(smem);

    const int tid    = threadIdx.x;
    const int lane   = tid & 31;
    const int warpId = tid >> 5;
    const int warp_m = warpId & 1;
    const int warp_n = warpId >> 1;

    const int blockN = blockIdx.x * BN;
    const int blockM = blockIdx.y * BM;

    const __half* Ab = A + (size_t)blockM * K;
    const __half* Bb = B + (size_t)blockN * K;

    float acc[4][4][4];
#pragma unroll
    for (int mt = 0; mt < 4; mt++)
#pragma unroll
        for (int nt = 0; nt < 4; nt++)
#pragma unroll
            for (int c = 0; c < 4; c++)
                acc[mt][nt][c] = 0.0f;

    auto load_stage = [&](int st, int slot) {
        const int k0 = st * BKH;
        __half* As = smem + slot * STG_H;
        __half* Bs = As + A_H;
#pragma unroll
        for (int i = 0; i < 4; i++) {
            int idx = tid + i * 256;
            int row = idx >> 3, c = idx & 7;
            cp16(As + row * LDH + c * 8, Ab + (size_t)row * K + k0 + c * 8);
        }
#pragma unroll
        for (int i = 0; i < 4; i++) {
            int idx = tid + i * 256;
            int row = idx >> 3, c = idx & 7;
            cp16(Bs + row * LDH + c * 8, Bb + (size_t)row * K + k0 + c * 8);
        }
        asm volatile("cp.async.commit_group;\n");
    };

    load_stage(0, 0);
    load_stage(1, 1);

    const int aBase = (warp_m * 64 + (lane & 15)) * LDH + (lane >> 4) * 8;
    const int bBase = (warp_n * 32 + (lane & 7) + ((lane >> 4) * 8)) * LDH
                    + ((lane >> 3) & 1) * 8;

    int cs = 0, ls = 2;
    for (int it = 0; it < NSTG; it++) {
        if (it + 2 < NSTG) asm volatile("cp.async.wait_group 1;\n");
        else               asm volatile("cp.async.wait_group 0;\n");
        __syncthreads();

        const uint32_t As_u = smem_u32 + (cs * STG_H) * 2;
        const uint32_t Bs_u = As_u + A_H * 2;

        // ---- ks = 0: LDSM first, then issue next-stage cp.async under its latency
        {
            uint32_t af[4][4];
#pragma unroll
            for (int mt = 0; mt < 4; mt++)
                ldsm_x4(af[mt][0], af[mt][1], af[mt][2], af[mt][3],
                        As_u + (aBase + mt * 16 * LDH) * 2);
            uint32_t bf[4][2];
#pragma unroll
            for (int p = 0; p < 2; p++)
                ldsm_x4(bf[2 * p][0], bf[2 * p][1], bf[2 * p + 1][0], bf[2 * p + 1][1],
                        Bs_u + (bBase + p * 16 * LDH) * 2);

            if (it + 2 < NSTG) load_stage(it + 2, ls);

#pragma unroll
            for (int mt = 0; mt < 4; mt++)
#pragma unroll
                for (int nt = 0; nt < 4; nt++)
                    mma_f16(acc[mt][nt], af[mt][0], af[mt][1], af[mt][2], af[mt][3],
                            bf[nt][0], bf[nt][1]);
        }

        // ---- ks = 1..3 unchanged
#pragma unroll
        for (int ks = 1; ks < BKH / 16; ks++) {
            uint32_t af[4][4];
#pragma unroll
            for (int mt = 0; mt < 4; mt++)
                ldsm_x4(af[mt][0], af[mt][1], af[mt][2], af[mt][3],
                        As_u + (aBase + mt * 16 * LDH + ks * 16) * 2);

            uint32_t bf[4][2];
#pragma unroll
            for (int p = 0; p < 2; p++)
                ldsm_x4(bf[2 * p][0], bf[2 * p][1], bf[2 * p + 1][0], bf[2 * p + 1][1],
                        Bs_u + (bBase + p * 16 * LDH + ks * 16) * 2);

#pragma unroll
            for (int mt = 0; mt < 4; mt++)
#pragma unroll
                for (int nt = 0; nt < 4; nt++)
                    mma_f16(acc[mt][nt], af[mt][0], af[mt][1], af[mt][2], af[mt][3],
                            bf[nt][0], bf[nt][1]);
        }

        cs = (cs == NSTAGE - 1) ? 0 : cs + 1;
        ls = (ls == NSTAGE - 1) ? 0 : ls + 1;
    }

    // ---- epilogue: segmented bias, strided C ----
    const int seg = blockN >> 10;
    const float* bias = (seg == 0) ? b0 : (seg == 1) ? b1 : b2;
    const int colSeg  = (blockN & 1023) + warp_n * 32 + (lane & 3) * 2;
    const int colGlb  = blockN + warp_n * 32 + (lane & 3) * 2;
    const int rowBase = blockM + warp_m * 64 + (lane >> 2);
#pragma unroll
    for (int nt = 0; nt < 4; nt++) {
        const float bv0 = bias[colSeg + nt * 8], bv1 = bias[colSeg + nt * 8 + 1];
#pragma unroll
        for (int mt = 0; mt < 4; mt++) {
            OutT* p0 = C + (size_t)(rowBase + mt * 16) * ldc + colGlb + nt * 8;
            OutT* p1 = C + (size_t)(rowBase + mt * 16 + 8) * ldc + colGlb + nt * 8;
            if constexpr (sizeof(OutT) == 4) {
                *reinterpret_cast<float2*>(p0) =
                    make_float2(acc[mt][nt][0] + bv0, acc[mt][nt][1] + bv1);
                *reinterpret_cast<float2*>(p1) =
                    make_float2(acc[mt][nt][2] + bv0, acc[mt][nt][3] + bv1);
            } else {
                *reinterpret_cast<__half2*>(p0) =
                    __floats2half2_rn(acc[mt][nt][0] + bv0, acc[mt][nt][1] + bv1);
                *reinterpret_cast<__half2*>(p1) =
                    __floats2half2_rn(acc[mt][nt][2] + bv0, acc[mt][nt][3] + bv1);
            }
        }
    }
}

// ---------------------------------------------------------------------------
// One-shot f32 -> f16: x followed by all 4 weight matrices (unrolled x4)
// ---------------------------------------------------------------------------
__global__ __launch_bounds__(256)
void f2h_all_kernel(const float4* __restrict__ x,
                    const float4* __restrict__ w0, const float4* __restrict__ w1,
                    const float4* __restrict__ w2, const float4* __restrict__ w3,
                    uint2* __restrict__ outx, uint2* __restrict__ outw,
                    int xn4, int wn4)
{
    const int total = xn4 + 4 * wn4;
#pragma unroll 4
    for (int i = blockIdx.x * blockDim.x + threadIdx.x; i < total;
         i += gridDim.x * blockDim.x) {
        float4 v;
        uint2* dst;
        if (i < xn4) {
            v = __ldg(x + i);
            dst = outx + i;
        } else {
            const int t = i - xn4;
            const int j = t / wn4;
            const int r = t - j * wn4;
            const float4* src = (j == 0) ? w0 : (j == 1) ? w1 : (j == 2) ? w2 : w3;
            v = __ldg(src + r);
            dst = outw + t;
        }
        __half2 h0 = __floats2half2_rn(v.x, v.y);
        __half2 h1 = __floats2half2_rn(v.z, v.w);
        uint2 o;
        o.x = h2u(h0); o.y = h2u(h1);
        *dst = o;
    }
}

// ---------------------------------------------------------------------------
// Tensor-core head-axis attention (R11 validated). One warp per token.
// ---------------------------------------------------------------------------
__global__ __launch_bounds__(256)
void attn_kernel(const __half* __restrict__ QKV, __half* __restrict__ Y)
{
    extern __shared__ __align__(16) __half asm_smem[];
    const int w    = threadIdx.x >> 5;
    const int lane = threadIdx.x & 31;
    const int token = blockIdx.x * 8 + w;

    __half* sQ = asm_smem + w * ATOK_H;
    __half* sK = sQ + 16 * ALD;
    __half* sV = sK + 16 * ALD;

    const __half* Qg = QKV + (size_t)token * N_QKV;
    const __half* Kg = Qg + E_DIM;
    const __half* Vg = Qg + 2 * E_DIM;

#pragma unroll
    for (int it = 0; it < 4; it++) {
        const int idx = it * 32 + lane;
        const int row = idx >> 3, c = idx & 7;
        *reinterpret_cast<uint4*>(sQ + row * ALD + c * 8) =
            *reinterpret_cast<const uint4*>(Qg + idx * 8);
        *reinterpret_cast<uint4*>(sK + row * ALD + c * 8) =
            *reinterpret_cast<const uint4*>(Kg + idx * 8);
        *reinterpret_cast<uint4*>(sV + row * ALD + c * 8) =
            *reinterpret_cast<const uint4*>(Vg + idx * 8);
    }
    __syncwarp();

    const uint32_t sQu = (uint32_t)__cvta_generic_to_shared(sQ);
    const uint32_t sKu = (uint32_t)__cvta_generic_to_shared(sK);
    const uint32_t sVu = (uint32_t)__cvta_generic_to_shared(sV);

    const uint32_t qBase = sQu + ((lane & 15) * ALD + (lane >> 4) * 8) * 2;
    const uint32_t kBase = sKu + (((lane & 7) + (lane >> 4) * 8) * ALD
                                  + ((lane >> 3) & 1) * 8) * 2;
    float en0[4] = {0.f, 0.f, 0.f, 0.f};
    float en1[4] = {0.f, 0.f, 0.f, 0.f};
#pragma unroll
    for (int kc = 0; kc < 4; kc++) {
        uint32_t a0, a1, a2, a3, b0, b1, b2, b3;
        ldsm_x4(a0, a1, a2, a3, qBase + kc * 32);
        ldsm_x4(b0, b1, b2, b3, kBase + kc * 32);
        mma_f16(en0, a0, a1, a2, a3, b0, b1);
        mma_f16(en1, a0, a1, a2, a3, b2, b3);
    }

    float rA[4] = {en0[0] * 0.03125f, en0[1] * 0.03125f,
                   en1[0] * 0.03125f, en1[1] * 0.03125f};
    float rB[4] = {en0[2] * 0.03125f, en0[3] * 0.03125f,
                   en1[2] * 0.03125f, en1[3] * 0.03125f};

    float mA = fmaxf(fmaxf(rA[0], rA[1]), fmaxf(rA[2], rA[3]));
    float mB = fmaxf(fmaxf(rB[0], rB[1]), fmaxf(rB[2], rB[3]));
    mA = fmaxf(mA, __shfl_xor_sync(0xffffffffu, mA, 1));
    mA = fmaxf(mA, __shfl_xor_sync(0xffffffffu, mA, 2));
    mB = fmaxf(mB, __shfl_xor_sync(0xffffffffu, mB, 1));
    mB = fmaxf(mB, __shfl_xor_sync(0xffffffffu, mB, 2));

    float sA = 0.f, sB = 0.f;
#pragma unroll
    for (int t = 0; t < 4; t++) {
        rA[t] = __expf(rA[t] - mA); sA += rA[t];
        rB[t] = __expf(rB[t] - mB); sB += rB[t];
    }
    sA += __shfl_xor_sync(0xffffffffu, sA, 1);
    sA += __shfl_xor_sync(0xffffffffu, sA, 2);
    sB += __shfl_xor_sync(0xffffffffu, sB, 1);
    sB += __shfl_xor_sync(0xffffffffu, sB, 2);
    const float iA = 1.0f / sA, iB = 1.0f / sB;

    const uint32_t pa0 = h2u(__floats2half2_rn(rA[0] * iA, rA[1] * iA));
    const uint32_t pa1 = h2u(__floats2half2_rn(rB[0] * iB, rB[1] * iB));
    const uint32_t pa2 = h2u(__floats2half2_rn(rA[2] * iA, rA[3] * iA));
    const uint32_t pa3 = h2u(__floats2half2_rn(rB[2] * iB, rB[3] * iB));

    const uint32_t vBase = sVu + (((lane & 7) + ((lane >> 3) & 1) * 8) * ALD
                                  + (lane >> 4) * 8) * 2;
    float o[8][4];
#pragma unroll
    for (int t = 0; t < 8; t++)
#pragma unroll
        for (int c = 0; c < 4; c++) o[t][c] = 0.f;

#pragma unroll
    for (int nt = 0; nt < 4; nt++) {
        uint32_t v0, v1, v2, v3;
        ldsm_x4_t(v0, v1, v2, v3, vBase + nt * 32);
        mma_f16(o[2 * nt],     pa0, pa1, pa2, pa3, v0, v1);
        mma_f16(o[2 * nt + 1], pa0, pa1, pa2, pa3, v2, v3);
    }

    const int nb = token / S_LEN;
    const int s  = token % S_LEN;
    const int i  = lane >> 2;
    const size_t baseA = ((size_t)(nb * S_LEN + i * 512 + (s >> 4))) * E_DIM
                       + (s & 15) * 64 + (lane & 3) * 2;
    const size_t baseB = ((size_t)(nb * S_LEN + (i + 8) * 512 + (s >> 4))) * E_DIM
                       + (s & 15) * 64 + (lane & 3) * 2;
#pragma unroll
    for (int t = 0; t < 8; t++) {
        *reinterpret_cast<__half2*>(Y + baseA + t * 8) =
            __floats2half2_rn(o[t][0], o[t][1]);
        *reinterpret_cast<__half2*>(Y + baseB + t * 8) =
            __floats2half2_rn(o[t][2], o[t][3]);
    }
}

// ---------------------------------------------------------------------------
// Launch
// ---------------------------------------------------------------------------
extern "C" void kernel_launch(void* const* d_in, const int* in_sizes, int n_in,
                              void* d_out, int out_size)
{
    const float* x  = (const float*)d_in[0];
    const float* Ws[4] = { (const float*)d_in[1], (const float*)d_in[2],
                           (const float*)d_in[3], (const float*)d_in[4] };
    const float* bq = (const float*)d_in[5];
    const float* bk = (const float*)d_in[6];
    const float* bv = (const float*)d_in[7];
    const float* bo = (const float*)d_in[8];
    float* out = (float*)d_out;

    __half *Xh, *Wh, *QKVh, *Yh;
    cudaGetSymbolAddress((void**)&Xh,   g_Xh);
    cudaGetSymbolAddress((void**)&Wh,   g_Wh);
    cudaGetSymbolAddress((void**)&QKVh, g_QKVh);
    cudaGetSymbolAddress((void**)&Yh,   g_Yh);

    static bool attr_set = false;
    if (!attr_set) {
        cudaFuncSetAttribute(hgemm_bias_kernel<__half>,
                             cudaFuncAttributeMaxDynamicSharedMemorySize, SMEM_BYTES);
        cudaFuncSetAttribute(hgemm_bias_kernel<float>,
                             cudaFuncAttributeMaxDynamicSharedMemorySize, SMEM_BYTES);
        cudaFuncSetAttribute(attn_kernel,
                             cudaFuncAttributeMaxDynamicSharedMemorySize, ATTN_SMEM);
        attr_set = true;
    }

    // 1) one-shot fp16 conversion (x + all weights)
    const int xn4 = (M_TOT * E_DIM) / 4;
    const int wn4 = (E_DIM * E_DIM) / 4;
    f2h_all_kernel<<<4096, 256>>>((const float4*)x,
                                  (const float4*)Ws[0], (const float4*)Ws[1],
                                  (const float4*)Ws[2], (const float4*)Ws[3],
                                  (uint2*)Xh, (uint2*)Wh, xn4, wn4);

    // 2) fused Q/K/V projection: [M,1024] @ [3072,1024]^T -> [M,3072] fp16
    dim3 gblock(256);
    dim3 gridQKV(N_QKV / BN, M_TOT / BM);
    hgemm_bias_kernel<__half><<<gridQKV, gblock, SMEM_BYTES>>>(
        Xh, Wh, bq, bk, bv, QKVh, M_TOT, N_QKV, E_DIM);

    // 3) tensor-core head-axis attention + scramble (8 tokens/block)
    attn_kernel<<<M_TOT / 8, 256, ATTN_SMEM>>>(QKVh, Yh);

    // 4) output projection (fp32 out)
    dim3 gridO(E_DIM / BN, M_TOT / BM);
    hgemm_bias_kernel<float><<<gridO, gblock, SMEM_BYTES>>>(
        Yh, Wh + 3 * (size_t)E_DIM * E_DIM, bo, bo, bo, out, M_TOT, E_DIM, E_DIM);
}

// round 14
// speedup vs baseline: 1.2345x; 1.0232x over previous
#include <cuda_runtime.h>
#include <cuda_fp16.h>
#include <cstdint>

// ---------------------------------------------------------------------------
// Problem constants
// ---------------------------------------------------------------------------
#define NB     4
#define S_LEN  8192
#define E_DIM  1024
#define M_TOT  (NB * S_LEN)   // 32768
#define M_HALF (M_TOT / 2)    // 16384
#define N_QKV  3072

// ---------------------------------------------------------------------------
// GEMM tiling: block 128x128, warp tile 64x32, BK=64 halves, 3-stage pipeline
// 2 CTAs/SM (regs ~128/thread)  [validated — mainloop unchanged since R13]
// ---------------------------------------------------------------------------
#define BM 128
#define BN 128
#define BKH 64
#define LDH 72
#define A_H (BM * LDH)
#define B_H (BN * LDH)
#define STG_H (A_H + B_H)
#define NSTAGE 3
#define SMEM_BYTES (NSTAGE * STG_H * 2)   // 110592 B -> 2 CTAs/SM
#define NSTG (E_DIM / BKH)

// attention smem
#define ALD 72
#define ATOK_H (3 * 16 * ALD)
#define ATTN_SMEM (8 * ATOK_H * 2)        // 55296 B

// ---------------------------------------------------------------------------
// Scratch
// ---------------------------------------------------------------------------
__device__ __half g_Xh[(size_t)M_TOT * E_DIM];
__device__ __half g_Wh[4][(size_t)E_DIM * E_DIM];
__device__ __half g_QKVh[(size_t)M_TOT * N_QKV];
__device__ __half g_Yh[(size_t)M_TOT * E_DIM];

// ---------------------------------------------------------------------------
// Helpers
// ---------------------------------------------------------------------------
__device__ __forceinline__ void cp16(void* dst_smem, const void* src_gmem) {
    uint32_t d = (uint32_t)__cvta_generic_to_shared(dst_smem);
    asm volatile("cp.async.cg.shared.global [%0], [%1], 16;\n" :: "r"(d), "l"(src_gmem));
}
__device__ __forceinline__ void ldsm_x4(uint32_t& r0, uint32_t& r1,
                                        uint32_t& r2, uint32_t& r3, uint32_t addr) {
    asm volatile("ldmatrix.sync.aligned.m8n8.x4.shared.b16 {%0,%1,%2,%3}, [%4];"
        : "=r"(r0), "=r"(r1), "=r"(r2), "=r"(r3) : "r"(addr));
}
__device__ __forceinline__ void ldsm_x4_t(uint32_t& r0, uint32_t& r1,
                                          uint32_t& r2, uint32_t& r3, uint32_t addr) {
    asm volatile("ldmatrix.sync.aligned.m8n8.x4.trans.shared.b16 {%0,%1,%2,%3}, [%4];"
        : "=r"(r0), "=r"(r1), "=r"(r2), "=r"(r3) : "r"(addr));
}
__device__ __forceinline__ void mma_f16(float c[4],
                                        uint32_t a0, uint32_t a1, uint32_t a2, uint32_t a3,
                                        uint32_t b0, uint32_t b1) {
    asm volatile(
        "mma.sync.aligned.m16n8k16.row.col.f32.f16.f16.f32 "
        "{%0,%1,%2,%3}, {%4,%5,%6,%7}, {%8,%9}, {%0,%1,%2,%3};\n"
        : "+f"(c[0]), "+f"(c[1]), "+f"(c[2]), "+f"(c[3])
        : "r"(a0), "r"(a1), "r"(a2), "r"(a3), "r"(b0), "r"(b1));
}
__device__ __forceinline__ uint32_t h2u(__half2 h) {
    return *reinterpret_cast<uint32_t*>(&h);
}

// ---------------------------------------------------------------------------
// fp16 tensor-core GEMM (R13 validated, unchanged)
// ---------------------------------------------------------------------------
template <typename OutT>
__global__ __launch_bounds__(256, 2)
void hgemm_bias_kernel(const __half* __restrict__ A,
                       const __half* __restrict__ B,
                       const float* __restrict__ b0,
                       const float* __restrict__ b1,
                       const float* __restrict__ b2,
                       OutT* __restrict__ C,
                       int M, int ldc, int K)
{
    extern __shared__ __align__(128) __half smem[];
    const uint32_t smem_u32 = (uint32_t)__cvta_generic_to_shared(smem);

    const int tid    = threadIdx.x;
    const int lane   = tid & 31;
    const int warpId = tid >> 5;
    const int warp_m = warpId & 1;
    const int warp_n = warpId >> 1;

    const int blockN = blockIdx.x * BN;
    const int blockM = blockIdx.y * BM;

    const __half* Ab = A + (size_t)blockM * K;
    const __half* Bb = B + (size_t)blockN * K;

    float acc[4][4][4];
#pragma unroll
    for (int mt = 0; mt < 4; mt++)
#pragma unroll
        for (int nt = 0; nt < 4; nt++)
#pragma unroll
            for (int c = 0; c < 4; c++)
                acc[mt][nt][c] = 0.0f;

    auto load_stage = [&](int st, int slot) {
        const int k0 = st * BKH;
        __half* As = smem + slot * STG_H;
        __half* Bs = As + A_H;
#pragma unroll
        for (int i = 0; i < 4; i++) {
            int idx = tid + i * 256;
            int row = idx >> 3, c = idx & 7;
            cp16(As + row * LDH + c * 8, Ab + (size_t)row * K + k0 + c * 8);
        }
#pragma unroll
        for (int i = 0; i < 4; i++) {
            int idx = tid + i * 256;
            int row = idx >> 3, c = idx & 7;
            cp16(Bs + row * LDH + c * 8, Bb + (size_t)row * K + k0 + c * 8);
        }
        asm volatile("cp.async.commit_group;\n");
    };

    load_stage(0, 0);
    load_stage(1, 1);

    const int aBase = (warp_m * 64 + (lane & 15)) * LDH + (lane >> 4) * 8;
    const int bBase = (warp_n * 32 + (lane & 7) + ((lane >> 4) * 8)) * LDH
                    + ((lane >> 3) & 1) * 8;

    int cs = 0, ls = 2;
    for (int it = 0; it < NSTG; it++) {
        if (it + 2 < NSTG) asm volatile("cp.async.wait_group 1;\n");
        else               asm volatile("cp.async.wait_group 0;\n");
        __syncthreads();

        const uint32_t As_u = smem_u32 + (cs * STG_H) * 2;
        const uint32_t Bs_u = As_u + A_H * 2;

        // ks = 0: LDSM first, next-stage cp.async issued under its latency
        {
            uint32_t af[4][4];
#pragma unroll
            for (int mt = 0; mt < 4; mt++)
                ldsm_x4(af[mt][0], af[mt][1], af[mt][2], af[mt][3],
                        As_u + (aBase + mt * 16 * LDH) * 2);
            uint32_t bf[4][2];
#pragma unroll
            for (int p = 0; p < 2; p++)
                ldsm_x4(bf[2 * p][0], bf[2 * p][1], bf[2 * p + 1][0], bf[2 * p + 1][1],
                        Bs_u + (bBase + p * 16 * LDH) * 2);

            if (it + 2 < NSTG) load_stage(it + 2, ls);

#pragma unroll
            for (int mt = 0; mt < 4; mt++)
#pragma unroll
                for (int nt = 0; nt < 4; nt++)
                    mma_f16(acc[mt][nt], af[mt][0], af[mt][1], af[mt][2], af[mt][3],
                            bf[nt][0], bf[nt][1]);
        }

#pragma unroll
        for (int ks = 1; ks < BKH / 16; ks++) {
            uint32_t af[4][4];
#pragma unroll
            for (int mt = 0; mt < 4; mt++)
                ldsm_x4(af[mt][0], af[mt][1], af[mt][2], af[mt][3],
                        As_u + (aBase + mt * 16 * LDH + ks * 16) * 2);

            uint32_t bf[4][2];
#pragma unroll
            for (int p = 0; p < 2; p++)
                ldsm_x4(bf[2 * p][0], bf[2 * p][1], bf[2 * p + 1][0], bf[2 * p + 1][1],
                        Bs_u + (bBase + p * 16 * LDH + ks * 16) * 2);

#pragma unroll
            for (int mt = 0; mt < 4; mt++)
#pragma unroll
                for (int nt = 0; nt < 4; nt++)
                    mma_f16(acc[mt][nt], af[mt][0], af[mt][1], af[mt][2], af[mt][3],
                            bf[nt][0], bf[nt][1]);
        }

        cs = (cs == NSTAGE - 1) ? 0 : cs + 1;
        ls = (ls == NSTAGE - 1) ? 0 : ls + 1;
    }

    const int seg = blockN >> 10;
    const float* bias = (seg == 0) ? b0 : (seg == 1) ? b1 : b2;
    const int colSeg  = (blockN & 1023) + warp_n * 32 + (lane & 3) * 2;
    const int colGlb  = blockN + warp_n * 32 + (lane & 3) * 2;
    const int rowBase = blockM + warp_m * 64 + (lane >> 2);
#pragma unroll
    for (int nt = 0; nt < 4; nt++) {
        const float bv0 = bias[colSeg + nt * 8], bv1 = bias[colSeg + nt * 8 + 1];
#pragma unroll
        for (int mt = 0; mt < 4; mt++) {
            OutT* p0 = C + (size_t)(rowBase + mt * 16) * ldc + colGlb + nt * 8;
            OutT* p1 = C + (size_t)(rowBase + mt * 16 + 8) * ldc + colGlb + nt * 8;
            if constexpr (sizeof(OutT) == 4) {
                *reinterpret_cast<float2*>(p0) =
                    make_float2(acc[mt][nt][0] + bv0, acc[mt][nt][1] + bv1);
                *reinterpret_cast<float2*>(p1) =
                    make_float2(acc[mt][nt][2] + bv0, acc[mt][nt][3] + bv1);
            } else {
                *reinterpret_cast<__half2*>(p0) =
                    __floats2half2_rn(acc[mt][nt][0] + bv0, acc[mt][nt][1] + bv1);
                *reinterpret_cast<__half2*>(p1) =
                    __floats2half2_rn(acc[mt][nt][2] + bv0, acc[mt][nt][3] + bv1);
            }
        }
    }
}

// ---------------------------------------------------------------------------
// f32 -> f16: generic contiguous range (used for x halves)
// ---------------------------------------------------------------------------
__global__ __launch_bounds__(256)
void f2h_x_kernel(const float4* __restrict__ in, uint2* __restrict__ out, int n4)
{
#pragma unroll 4
    for (int i = blockIdx.x * blockDim.x + threadIdx.x; i < n4;
         i += gridDim.x * blockDim.x) {
        float4 v = __ldg(in + i);
        __half2 h0 = __floats2half2_rn(v.x, v.y);
        __half2 h1 = __floats2half2_rn(v.z, v.w);
        uint2 o;
        o.x = h2u(h0); o.y = h2u(h1);
        out[i] = o;
    }
}

// f32 -> f16: all 4 weight matrices
__global__ __launch_bounds__(256)
void f2h_w_kernel(const float4* __restrict__ w0, const float4* __restrict__ w1,
                  const float4* __restrict__ w2, const float4* __restrict__ w3,
                  uint2* __restrict__ out, int wn4)
{
    const int total = 4 * wn4;
#pragma unroll 4
    for (int i = blockIdx.x * blockDim.x + threadIdx.x; i < total;
         i += gridDim.x * blockDim.x) {
        const int j = i / wn4;
        const int r = i - j * wn4;
        const float4* src = (j == 0) ? w0 : (j == 1) ? w1 : (j == 2) ? w2 : w3;
        float4 v = __ldg(src + r);
        __half2 h0 = __floats2half2_rn(v.x, v.y);
        __half2 h1 = __floats2half2_rn(v.z, v.w);
        uint2 o;
        o.x = h2u(h0); o.y = h2u(h1);
        out[i] = o;
    }
}

// ---------------------------------------------------------------------------
// Tensor-core head-axis attention (R11 validated) + token offset for M-split
// ---------------------------------------------------------------------------
__global__ __launch_bounds__(256)
void attn_kernel(const __half* __restrict__ QKV, __half* __restrict__ Y, int tokBase)
{
    extern __shared__ __align__(16) __half asm_smem[];
    const int w    = threadIdx.x >> 5;
    const int lane = threadIdx.x & 31;
    const int token = tokBase + blockIdx.x * 8 + w;

    __half* sQ = asm_smem + w * ATOK_H;
    __half* sK = sQ + 16 * ALD;
    __half* sV = sK + 16 * ALD;

    const __half* Qg = QKV + (size_t)token * N_QKV;
    const __half* Kg = Qg + E_DIM;
    const __half* Vg = Qg + 2 * E_DIM;

#pragma unroll
    for (int it = 0; it < 4; it++) {
        const int idx = it * 32 + lane;
        const int row = idx >> 3, c = idx & 7;
        *reinterpret_cast<uint4*>(sQ + row * ALD + c * 8) =
            *reinterpret_cast<const uint4*>(Qg + idx * 8);
        *reinterpret_cast<uint4*>(sK + row * ALD + c * 8) =
            *reinterpret_cast<const uint4*>(Kg + idx * 8);
        *reinterpret_cast<uint4*>(sV + row * ALD + c * 8) =
            *reinterpret_cast<const uint4*>(Vg + idx * 8);
    }
    __syncwarp();

    const uint32_t sQu = (uint32_t)__cvta_generic_to_shared(sQ);
    const uint32_t sKu = (uint32_t)__cvta_generic_to_shared(sK);
    const uint32_t sVu = (uint32_t)__cvta_generic_to_shared(sV);

    const uint32_t qBase = sQu + ((lane & 15) * ALD + (lane >> 4) * 8) * 2;
    const uint32_t kBase = sKu + (((lane & 7) + (lane >> 4) * 8) * ALD
                                  + ((lane >> 3) & 1) * 8) * 2;
    float en0[4] = {0.f, 0.f, 0.f, 0.f};
    float en1[4] = {0.f, 0.f, 0.f, 0.f};
#pragma unroll
    for (int kc = 0; kc < 4; kc++) {
        uint32_t a0, a1, a2, a3, b0, b1, b2, b3;
        ldsm_x4(a0, a1, a2, a3, qBase + kc * 32);
        ldsm_x4(b0, b1, b2, b3, kBase + kc * 32);
        mma_f16(en0, a0, a1, a2, a3, b0, b1);
        mma_f16(en1, a0, a1, a2, a3, b2, b3);
    }

    float rA[4] = {en0[0] * 0.03125f, en0[1] * 0.03125f,
                   en1[0] * 0.03125f, en1[1] * 0.03125f};
    float rB[4] = {en0[2] * 0.03125f, en0[3] * 0.03125f,
                   en1[2] * 0.03125f, en1[3] * 0.03125f};

    float mA = fmaxf(fmaxf(rA[0], rA[1]), fmaxf(rA[2], rA[3]));
    float mB = fmaxf(fmaxf(rB[0], rB[1]), fmaxf(rB[2], rB[3]));
    mA = fmaxf(mA, __shfl_xor_sync(0xffffffffu, mA, 1));
    mA = fmaxf(mA, __shfl_xor_sync(0xffffffffu, mA, 2));
    mB = fmaxf(mB, __shfl_xor_sync(0xffffffffu, mB, 1));
    mB = fmaxf(mB, __shfl_xor_sync(0xffffffffu, mB, 2));

    float sA = 0.f, sB = 0.f;
#pragma unroll
    for (int t = 0; t < 4; t++) {
        rA[t] = __expf(rA[t] - mA); sA += rA[t];
        rB[t] = __expf(rB[t] - mB); sB += rB[t];
    }
    sA += __shfl_xor_sync(0xffffffffu, sA, 1);
    sA += __shfl_xor_sync(0xffffffffu, sA, 2);
    sB += __shfl_xor_sync(0xffffffffu, sB, 1);
    sB += __shfl_xor_sync(0xffffffffu, sB, 2);
    const float iA = 1.0f / sA, iB = 1.0f / sB;

    const uint32_t pa0 = h2u(__floats2half2_rn(rA[0] * iA, rA[1] * iA));
    const uint32_t pa1 = h2u(__floats2half2_rn(rB[0] * iB, rB[1] * iB));
    const uint32_t pa2 = h2u(__floats2half2_rn(rA[2] * iA, rA[3] * iA));
    const uint32_t pa3 = h2u(__floats2half2_rn(rB[2] * iB, rB[3] * iB));

    const uint32_t vBase = sVu + (((lane & 7) + ((lane >> 3) & 1) * 8) * ALD
                                  + (lane >> 4) * 8) * 2;
    float o[8][4];
#pragma unroll
    for (int t = 0; t < 8; t++)
#pragma unroll
        for (int c = 0; c < 4; c++) o[t][c] = 0.f;

#pragma unroll
    for (int nt = 0; nt < 4; nt++) {
        uint32_t v0, v1, v2, v3;
        ldsm_x4_t(v0, v1, v2, v3, vBase + nt * 32);
        mma_f16(o[2 * nt],     pa0, pa1, pa2, pa3, v0, v1);
        mma_f16(o[2 * nt + 1], pa0, pa1, pa2, pa3, v2, v3);
    }

    const int nb = token / S_LEN;
    const int s  = token % S_LEN;
    const int i  = lane >> 2;
    const size_t baseA = ((size_t)(nb * S_LEN + i * 512 + (s >> 4))) * E_DIM
                       + (s & 15) * 64 + (lane & 3) * 2;
    const size_t baseB = ((size_t)(nb * S_LEN + (i + 8) * 512 + (s >> 4))) * E_DIM
                       + (s & 15) * 64 + (lane & 3) * 2;
#pragma unroll
    for (int t = 0; t < 8; t++) {
        *reinterpret_cast<__half2*>(Y + baseA + t * 8) =
            __floats2half2_rn(o[t][0], o[t][1]);
        *reinterpret_cast<__half2*>(Y + baseB + t * 8) =
            __floats2half2_rn(o[t][2], o[t][3]);
    }
}

// ---------------------------------------------------------------------------
// Launch: two-stream fork/join, each stream owns one token half end-to-end.
// ---------------------------------------------------------------------------
extern "C" void kernel_launch(void* const* d_in, const int* in_sizes, int n_in,
                              void* d_out, int out_size)
{
    const float* x  = (const float*)d_in[0];
    const float* Ws[4] = { (const float*)d_in[1], (const float*)d_in[2],
                           (const float*)d_in[3], (const float*)d_in[4] };
    const float* bq = (const float*)d_in[5];
    const float* bk = (const float*)d_in[6];
    const float* bv = (const float*)d_in[7];
    const float* bo = (const float*)d_in[8];
    float* out = (float*)d_out;

    __half *Xh, *Wh, *QKVh, *Yh;
    cudaGetSymbolAddress((void**)&Xh,   g_Xh);
    cudaGetSymbolAddress((void**)&Wh,   g_Wh);
    cudaGetSymbolAddress((void**)&QKVh, g_QKVh);
    cudaGetSymbolAddress((void**)&Yh,   g_Yh);

    static bool init_done = false;
    static cudaStream_t s1;
    static cudaEvent_t evW, evJ;
    if (!init_done) {
        cudaFuncSetAttribute(hgemm_bias_kernel<__half>,
                             cudaFuncAttributeMaxDynamicSharedMemorySize, SMEM_BYTES);
        cudaFuncSetAttribute(hgemm_bias_kernel<float>,
                             cudaFuncAttributeMaxDynamicSharedMemorySize, SMEM_BYTES);
        cudaFuncSetAttribute(attn_kernel,
                             cudaFuncAttributeMaxDynamicSharedMemorySize, ATTN_SMEM);
        cudaStreamCreateWithFlags(&s1, cudaStreamNonBlocking);
        cudaEventCreateWithFlags(&evW, cudaEventDisableTiming);
        cudaEventCreateWithFlags(&evJ, cudaEventDisableTiming);
        init_done = true;
    }

    const int xn4h = (M_HALF * E_DIM) / 4;
    const int wn4  = (E_DIM * E_DIM) / 4;
    const size_t xOffF4 = (size_t)xn4h;             // float4 offset for half 1
    const size_t whOff  = 3 * (size_t)E_DIM * E_DIM;

    dim3 gblock(256);
    dim3 gridQKVh(N_QKV / BN, M_HALF / BM);
    dim3 gridOh(E_DIM / BN, M_HALF / BM);

    // ---- S0: weights, then half-0 chain ----
    f2h_w_kernel<<<1024, 256, 0, 0>>>((const float4*)Ws[0], (const float4*)Ws[1],
                                      (const float4*)Ws[2], (const float4*)Ws[3],
                                      (uint2*)Wh, wn4);
    cudaEventRecord(evW, 0);

    f2h_x_kernel<<<2048, 256, 0, 0>>>((const float4*)x, (uint2*)Xh, xn4h);
    hgemm_bias_kernel<__half><<<gridQKVh, gblock, SMEM_BYTES, 0>>>(
        Xh, Wh, bq, bk, bv, QKVh, M_HALF, N_QKV, E_DIM);
    attn_kernel<<<M_HALF / 8, 256, ATTN_SMEM, 0>>>(QKVh, Yh, 0);
    hgemm_bias_kernel<float><<<gridOh, gblock, SMEM_BYTES, 0>>>(
        Yh, Wh + whOff, bo, bo, bo, out, M_HALF, E_DIM, E_DIM);

    // ---- S1: half-1 chain (waits only on weights) ----
    cudaStreamWaitEvent(s1, evW, 0);
    f2h_x_kernel<<<2048, 256, 0, s1>>>((const float4*)x + xOffF4,
                                       (uint2*)Xh + xOffF4, xn4h);
    hgemm_bias_kernel<__half><<<gridQKVh, gblock, SMEM_BYTES, s1>>>(
        Xh + (size_t)M_HALF * E_DIM, Wh, bq, bk, bv,
        QKVh + (size_t)M_HALF * N_QKV, M_HALF, N_QKV, E_DIM);
    attn_kernel<<<M_HALF / 8, 256, ATTN_SMEM, s1>>>(QKVh, Yh, M_HALF);
    hgemm_bias_kernel<float><<<gridOh, gblock, SMEM_BYTES, s1>>>(
        Yh + (size_t)M_HALF * E_DIM, Wh + whOff, bo, bo, bo,
        out + (size_t)M_HALF * E_DIM, M_HALF, E_DIM, E_DIM);
    cudaEventRecord(evJ, s1);

    // ---- join ----
    cudaStreamWaitEvent(0, evJ, 0);
}